// round 12
// baseline (speedup 1.0000x reference)
#include <cuda_runtime.h>
#include <cuda_fp16.h>
#include <cstdint>
#include <math.h>

#define BSZ 1024
#define TT  256
#define DIN0 6
#define HH  128
#define LN_EPS 1e-5f

// ---------------- scratch (device globals; no allocations allowed) ----------------
__device__ float  d_xn[BSZ * TT * DIN0];             // layer-normed input
__device__ __half d_h0h[(size_t)BSZ * TT * 256];     // layer0 output (fp16)
__device__ __half d_h1h[(size_t)BSZ * TT * 256];     // layer1 output (fp16)
__device__ __half d_xph[(size_t)BSZ * TT * 1024];    // layer1 pre-activations (fp16)
__device__ float  d_scores[BSZ * TT];
// packed weights
__device__ float  d_b0[2 * 512];
__device__ float  d_b1[2 * 512];
__device__ __half d_W16[1024 * 256];                 // layer1 Wih fp16 [n=dir*512+jg][k]
__device__ __half d_W0cat[2 * 512 * 144];            // layer0 [Whh | Wih0 | 0pad] fp16
__device__ __half d_Whh1h[2 * 512 * 128];            // layer1 Whh fp16 [dir][jg][k]
__device__ __half d_Wa16[128 * 256];                 // Wa1 fp16 [n][k] row-major

// ---------------- activation helpers ----------------
__device__ __forceinline__ float tanh_fast(float x) {
    float y;
    asm("tanh.approx.f32 %0, %1;" : "=f"(y) : "f"(x));
    return y;
}
__device__ __forceinline__ float sig_fast(float x) {
    return fmaf(0.5f, tanh_fast(0.5f * x), 0.5f);
}

__device__ __forceinline__ void cp16(void* smem_dst, const void* gsrc) {
    uint32_t s = (uint32_t)__cvta_generic_to_shared(smem_dst);
    asm volatile("cp.async.cg.shared.global [%0], [%1], 16;\n" :: "r"(s), "l"(gsrc));
}
__device__ __forceinline__ void cp8(void* smem_dst, const void* gsrc) {
    uint32_t s = (uint32_t)__cvta_generic_to_shared(smem_dst);
    asm volatile("cp.async.ca.shared.global [%0], [%1], 8;\n" :: "r"(s), "l"(gsrc));
}

// ---------------- weight packing ----------------
__global__ void pack_kernel(const float* __restrict__ Wih0, const float* __restrict__ Whh0,
                            const float* __restrict__ bih0, const float* __restrict__ bhh0,
                            const float* __restrict__ Wih1, const float* __restrict__ Whh1,
                            const float* __restrict__ bih1, const float* __restrict__ bhh1,
                            const float* __restrict__ Wa1) {
    int i = blockIdx.x * blockDim.x + threadIdx.x;
    const int total = 2 * 256 * 512;
    for (; i < total; i += gridDim.x * blockDim.x) {
        int d   = i / (256 * 512);
        int rem = i - d * (256 * 512);
        int k   = rem >> 9;          // 0..255
        int jg  = rem & 511;         // j*4+g
        int j   = jg >> 2;
        int g   = jg & 3;
        int gi  = g * 128 + j;       // PyTorch gate row (i,f,g,o blocks of 128)
        d_W16[(size_t)(d * 512 + jg) * 256 + k] = __float2half(Wih1[(d * 512 + gi) * 256 + k]);
        if (i < 128 * 256)
            d_Wa16[i] = __float2half(Wa1[i]);
        if (k < 128)
            d_Whh1h[(d * 512 + jg) * 128 + k] = __float2half(Whh1[(d * 512 + gi) * 128 + k]);
        if (k < 144) {
            float v;
            if (k < 128)        v = Whh0[(d * 512 + gi) * 128 + k];
            else if (k < 128 + DIN0) v = Wih0[(d * 512 + gi) * DIN0 + (k - 128)];
            else                v = 0.f;
            d_W0cat[(d * 512 + jg) * 144 + k] = __float2half(v);
        }
        if (k == 0) {
            d_b0[d * 512 + jg] = bih0[d * 512 + gi] + bhh0[d * 512 + gi];
            d_b1[d * 512 + jg] = bih1[d * 512 + gi] + bhh1[d * 512 + gi];
        }
    }
}

// ---------------- input layernorm (over last dim = 6) ----------------
__global__ void ln_kernel(const float* __restrict__ x,
                          const float* __restrict__ g,
                          const float* __restrict__ b) {
    int row = blockIdx.x * blockDim.x + threadIdx.x;
    if (row >= BSZ * TT) return;
    const float* xr = x + (size_t)row * DIN0;
    float v[DIN0];
    float mu = 0.f;
#pragma unroll
    for (int k = 0; k < DIN0; ++k) { v[k] = xr[k]; mu += v[k]; }
    mu *= (1.f / DIN0);
    float var = 0.f;
#pragma unroll
    for (int k = 0; k < DIN0; ++k) { float d = v[k] - mu; var += d * d; }
    var *= (1.f / DIN0);
    float inv = rsqrtf(var + LN_EPS);
#pragma unroll
    for (int k = 0; k < DIN0; ++k)
        d_xn[(size_t)row * DIN0 + k] = (v[k] - mu) * inv * g[k] + b[k];
}

// ---------------- tensor-core BiLSTM recurrence v2 (unchanged from R9) ----------------
#define XPST 516

template <int LAYER>
__global__ __launch_bounds__(512, 1)
void lstm_tc2_kernel(const float* __restrict__ xn,     // L0 input [B][T][6]
                     const __half* __restrict__ xph,   // L1 input xp [B*T][1024]
                     const __half* __restrict__ Wmat,  // L0: [2][512][144]; L1: [2][512][128]
                     const float* __restrict__ biasp,  // [2][512]
                     __half* __restrict__ hout) {      // [B][T][256] fp16
    constexpr int KDIM = (LAYER == 0) ? 144 : 128;
    constexpr int KC   = KDIM / 16;
    constexpr int BSTX = (LAYER == 0) ? 152 : 136;

    extern __shared__ __align__(16) unsigned char smraw[];
    __half* Bs = reinterpret_cast<__half*>(smraw);     // [512][BSTX]
    __half* Hs = Bs + 512 * BSTX;                      // [2][16][BSTX]
    __half* Xp = Hs + 2 * 16 * BSTX;                   // [2][16][XPST] (L1 only)

    const int tid  = threadIdx.x;
    const int warp = tid >> 5;
    const int lane = tid & 31;
    const int dir  = blockIdx.y;
    const int bb0  = blockIdx.x * 16;
    const int j    = tid & 127;
    const int rg   = tid >> 7;
    const int nb0  = warp * 32;
    const int half = dir * 128;

    {
        const __half* src = Wmat + (size_t)dir * 512 * KDIM;
        constexpr int CH = KDIM / 8;
        for (int i = tid; i < 512 * CH; i += 512) {
            int n = i / CH, seg = i - n * CH;
            cp16(&Bs[n * BSTX + seg * 8], src + (size_t)n * KDIM + seg * 8);
        }
    }
    for (int i = tid; i < 2 * 16 * BSTX; i += 512) Hs[i] = __float2half(0.f);

    {
        const int tt0 = dir ? (TT - 1) : 0;
        if (LAYER == 0) {
            if (tid < 16 * DIN0) {
                int r = tid / DIN0, k = tid - r * DIN0;
                Hs[r * BSTX + 128 + k] =
                    __float2half(xn[((size_t)(bb0 + r) * TT + tt0) * DIN0 + k]);
            }
        } else {
#pragma unroll
            for (int rr = 0; rr < 4; ++rr) {
                int row = rg * 4 + rr;
                cp8(&Xp[row * XPST + j * 4],
                    &xph[((size_t)(bb0 + row) * TT + tt0) * 1024 + half * 4 + j * 4]);
            }
            asm volatile("cp.async.commit_group;\n");
        }
    }
    asm volatile("cp.async.wait_group 0;\n" ::: "memory");

    const int joff = (lane & 3) >> 1;
    float4 bq[4];
#pragma unroll
    for (int q = 0; q < 4; ++q)
        bq[q] = reinterpret_cast<const float4*>(biasp + dir * 512)[warp * 8 + 2 * q + joff];

    const bool evenlane = (lane & 1) == 0;
    const int r_base = lane >> 2;

    float c[4] = {0.f, 0.f, 0.f, 0.f};
    __syncthreads();

    for (int s = 0; s < TT; ++s) {
        const int cur = s & 1, nxt = (s + 1) & 1;

        if (s + 1 < TT) {
            const int ttn = dir ? (TT - 2 - s) : (s + 1);
            if (LAYER == 0) {
                if (tid < 16 * DIN0) {
                    int r = tid / DIN0, k = tid - r * DIN0;
                    Hs[nxt * 16 * BSTX + r * BSTX + 128 + k] =
                        __float2half(xn[((size_t)(bb0 + r) * TT + ttn) * DIN0 + k]);
                }
            } else {
#pragma unroll
                for (int rr = 0; rr < 4; ++rr) {
                    int row = rg * 4 + rr;
                    cp8(&Xp[nxt * 16 * XPST + row * XPST + j * 4],
                        &xph[((size_t)(bb0 + row) * TT + ttn) * 1024 + half * 4 + j * 4]);
                }
            }
        }
        if (LAYER == 1) asm volatile("cp.async.commit_group;\n");

        if (s > 0) {
            const int tts = dir ? (TT - s) : (s - 1);
#pragma unroll
            for (int rr = 0; rr < 4; ++rr) {
                int row = rg * 4 + rr;
                hout[((size_t)(bb0 + row) * TT + tts) * 256 + half + j] =
                    Hs[cur * 16 * BSTX + row * BSTX + j];
            }
        }

        float acc[4][4];
#pragma unroll
        for (int q = 0; q < 4; ++q) { acc[q][0] = acc[q][1] = acc[q][2] = acc[q][3] = 0.f; }

        const __half* hsc = Hs + cur * 16 * BSTX;
#pragma unroll
        for (int kc = 0; kc < KC; ++kc) {
            uint32_t ra0, ra1, ra2, ra3;
            uint32_t sa = (uint32_t)__cvta_generic_to_shared(
                &hsc[(lane & 15) * BSTX + (lane >> 4) * 8 + kc * 16]);
            asm volatile("ldmatrix.sync.aligned.m8n8.x4.shared.b16 {%0,%1,%2,%3},[%4];"
                         : "=r"(ra0), "=r"(ra1), "=r"(ra2), "=r"(ra3) : "r"(sa));
#pragma unroll
            for (int nb = 0; nb < 2; ++nb) {
                uint32_t rb0, rb1, rb2, rb3;
                uint32_t sb = (uint32_t)__cvta_generic_to_shared(
                    &Bs[(nb0 + nb * 16 + ((lane >> 4) & 1) * 8 + (lane & 7)) * BSTX +
                        ((lane >> 3) & 1) * 8 + kc * 16]);
                asm volatile("ldmatrix.sync.aligned.m8n8.x4.shared.b16 {%0,%1,%2,%3},[%4];"
                             : "=r"(rb0), "=r"(rb1), "=r"(rb2), "=r"(rb3) : "r"(sb));
                asm volatile("mma.sync.aligned.m16n8k16.row.col.f32.f16.f16.f32 "
                             "{%0,%1,%2,%3},{%4,%5,%6,%7},{%8,%9},{%0,%1,%2,%3};"
                             : "+f"(acc[nb * 2][0]), "+f"(acc[nb * 2][1]),
                               "+f"(acc[nb * 2][2]), "+f"(acc[nb * 2][3])
                             : "r"(ra0), "r"(ra1), "r"(ra2), "r"(ra3), "r"(rb0), "r"(rb1));
                asm volatile("mma.sync.aligned.m16n8k16.row.col.f32.f16.f16.f32 "
                             "{%0,%1,%2,%3},{%4,%5,%6,%7},{%8,%9},{%0,%1,%2,%3};"
                             : "+f"(acc[nb * 2 + 1][0]), "+f"(acc[nb * 2 + 1][1]),
                               "+f"(acc[nb * 2 + 1][2]), "+f"(acc[nb * 2 + 1][3])
                             : "r"(ra0), "r"(ra1), "r"(ra2), "r"(ra3), "r"(rb2), "r"(rb3));
            }
        }

        __half* hsn = Hs + nxt * 16 * BSTX;
#pragma unroll
        for (int q = 0; q < 4; ++q) {
            float s0 = evenlane ? acc[q][2] : acc[q][0];
            float s1 = evenlane ? acc[q][3] : acc[q][1];
            float t0 = __shfl_xor_sync(0xffffffffu, s0, 1);
            float t1 = __shfl_xor_sync(0xffffffffu, s1, 1);
            float gi, gf, gg, go;
            int row;
            if (evenlane) { gi = acc[q][0]; gf = acc[q][1]; gg = t0; go = t1; row = r_base; }
            else          { gi = t0; gf = t1; gg = acc[q][2]; go = acc[q][3]; row = r_base + 8; }
            const int jq = warp * 8 + 2 * q + joff;

            float ai = gi + bq[q].x;
            float af = gf + bq[q].y;
            float ag = gg + bq[q].z;
            float ao = go + bq[q].w;
            if (LAYER == 1) {
                float2 xr = *reinterpret_cast<const float2*>(
                    &Xp[cur * 16 * XPST + row * XPST + jq * 4]);
                __half2 x01 = *reinterpret_cast<const __half2*>(&xr.x);
                __half2 x23 = *reinterpret_cast<const __half2*>(&xr.y);
                ai += __low2float(x01);  af += __high2float(x01);
                ag += __low2float(x23);  ao += __high2float(x23);
            }
            float ii = sig_fast(ai);
            float ff = sig_fast(af);
            float G  = tanh_fast(ag);
            float oo = sig_fast(ao);
            c[q] = ff * c[q] + ii * G;
            float hv = oo * tanh_fast(c[q]);
            hsn[row * BSTX + jq] = __float2half(hv);
        }

        if (LAYER == 1) asm volatile("cp.async.wait_group 0;\n" ::: "memory");
        __syncthreads();
    }

    {
        const int tts = dir ? 0 : (TT - 1);
#pragma unroll
        for (int rr = 0; rr < 4; ++rr) {
            int row = rg * 4 + rr;
            hout[((size_t)(bb0 + row) * TT + tts) * 256 + half + j] =
                Hs[((TT) & 1) * 16 * BSTX + row * BSTX + j];
        }
    }
}

#define LSTM0_SMEM ((512 * 152 + 2 * 16 * 152) * 2)
#define LSTM1_SMEM ((512 * 136 + 2 * 16 * 136) * 2 + 2 * 16 * XPST * 2)

// ================= xp GEMM v3: resident-B persistent m-loop, 16 warps =================
// C[M,1024] = A[M,256] * Bw[1024,256]^T.  Grid (8 n-tiles, 128 m-groups).
// Each CTA (512 thr): B tile [128][256] staged ONCE; 16 m-subtiles of 128 rows, A full-K
// resident double-buffered via cp.async. 16 warps, warp tile 32M x 32N (4 warps/SMSP).
#define G2ST 264
#define GEMM2_SMEM (3 * 128 * G2ST * 2)   // 202752 bytes

__device__ __forceinline__ void g2_stage(__half* dst, const __half* g, int tid) {
#pragma unroll
    for (int it = 0; it < 8; ++it) {
        int i = tid + it * 512;
        int row = i >> 5, seg = i & 31;
        cp16(&dst[row * G2ST + seg * 8], g + (size_t)row * 256 + seg * 8);
    }
}

__global__ __launch_bounds__(512, 1)
void xp_gemm2_kernel(const __half* __restrict__ A,   // [M][256]
                     const __half* __restrict__ Bw,  // [1024][256]
                     __half* __restrict__ C) {       // [M][1024] fp16
    extern __shared__ __align__(16) __half sm[];
    __half* Bs = sm;                   // [128][G2ST]
    __half* As = sm + 128 * G2ST;      // [2][128][G2ST]

    const int tid  = threadIdx.x;
    const int warp = tid >> 5;
    const int lane = tid & 31;
    const int warpM = warp >> 2;       // 0..3 -> m offset *32
    const int warpN = warp & 3;        // 0..3 -> n offset *32
    const int    nBase = blockIdx.x * 128;
    const size_t mGrp  = (size_t)blockIdx.y * 16;    // first m-subtile

    // prologue: B + A(0) in group0, A(1) in group1
    g2_stage(Bs, Bw + (size_t)nBase * 256, tid);
    g2_stage(As, A + mGrp * 128 * 256, tid);
    asm volatile("cp.async.commit_group;\n");
    g2_stage(As + 128 * G2ST, A + (mGrp + 1) * 128 * 256, tid);
    asm volatile("cp.async.commit_group;\n");

    for (int t = 0; t < 16; ++t) {
        if (t < 15) asm volatile("cp.async.wait_group 1;\n");
        else        asm volatile("cp.async.wait_group 0;\n");
        __syncthreads();

        const __half* as = As + (t & 1) * 128 * G2ST;
        float acc[8][4];
#pragma unroll
        for (int q = 0; q < 8; ++q) { acc[q][0] = acc[q][1] = acc[q][2] = acc[q][3] = 0.f; }

#pragma unroll
        for (int kf = 0; kf < 16; ++kf) {
            uint32_t ra[2][4];
#pragma unroll
            for (int mf = 0; mf < 2; ++mf) {
                uint32_t saddrA = (uint32_t)__cvta_generic_to_shared(
                    &as[(warpM * 32 + mf * 16 + (lane & 15)) * G2ST +
                        (lane >> 4) * 8 + kf * 16]);
                asm volatile("ldmatrix.sync.aligned.m8n8.x4.shared.b16 {%0,%1,%2,%3},[%4];"
                             : "=r"(ra[mf][0]), "=r"(ra[mf][1]),
                               "=r"(ra[mf][2]), "=r"(ra[mf][3]) : "r"(saddrA));
            }
#pragma unroll
            for (int nb = 0; nb < 2; ++nb) {
                uint32_t rb0, rb1, rb2, rb3;
                uint32_t saddrB = (uint32_t)__cvta_generic_to_shared(
                    &Bs[(warpN * 32 + nb * 16 + ((lane >> 4) & 1) * 8 + (lane & 7)) * G2ST +
                        ((lane >> 3) & 1) * 8 + kf * 16]);
                asm volatile("ldmatrix.sync.aligned.m8n8.x4.shared.b16 {%0,%1,%2,%3},[%4];"
                             : "=r"(rb0), "=r"(rb1), "=r"(rb2), "=r"(rb3) : "r"(saddrB));
#pragma unroll
                for (int mf = 0; mf < 2; ++mf) {
                    asm volatile("mma.sync.aligned.m16n8k16.row.col.f32.f16.f16.f32 "
                                 "{%0,%1,%2,%3},{%4,%5,%6,%7},{%8,%9},{%0,%1,%2,%3};"
                                 : "+f"(acc[mf * 4 + nb * 2][0]), "+f"(acc[mf * 4 + nb * 2][1]),
                                   "+f"(acc[mf * 4 + nb * 2][2]), "+f"(acc[mf * 4 + nb * 2][3])
                                 : "r"(ra[mf][0]), "r"(ra[mf][1]), "r"(ra[mf][2]), "r"(ra[mf][3]),
                                   "r"(rb0), "r"(rb1));
                    asm volatile("mma.sync.aligned.m16n8k16.row.col.f32.f16.f16.f32 "
                                 "{%0,%1,%2,%3},{%4,%5,%6,%7},{%8,%9},{%0,%1,%2,%3};"
                                 : "+f"(acc[mf * 4 + nb * 2 + 1][0]), "+f"(acc[mf * 4 + nb * 2 + 1][1]),
                                   "+f"(acc[mf * 4 + nb * 2 + 1][2]), "+f"(acc[mf * 4 + nb * 2 + 1][3])
                                 : "r"(ra[mf][0]), "r"(ra[mf][1]), "r"(ra[mf][2]), "r"(ra[mf][3]),
                                   "r"(rb2), "r"(rb3));
                }
            }
        }

        // epilogue for tile t (global stores; no smem)
        {
            const size_t rowA = (mGrp + t) * 128 + warpM * 32 + (lane >> 2);
            const int    colA = nBase + warpN * 32 + (lane & 3) * 2;
#pragma unroll
            for (int mf = 0; mf < 2; ++mf) {
#pragma unroll
                for (int nb = 0; nb < 2; ++nb) {
#pragma unroll
                    for (int h = 0; h < 2; ++h) {
                        const int q = mf * 4 + nb * 2 + h;
                        const size_t r0 = rowA + mf * 16;
                        const int    cc = colA + nb * 16 + h * 8;
                        *reinterpret_cast<__half2*>(&C[r0 * 1024 + cc]) =
                            __floats2half2_rn(acc[q][0], acc[q][1]);
                        *reinterpret_cast<__half2*>(&C[(r0 + 8) * 1024 + cc]) =
                            __floats2half2_rn(acc[q][2], acc[q][3]);
                    }
                }
            }
        }
        __syncthreads();   // all reads of As[t&1] done before restage

        if (t + 2 < 16)
            g2_stage(As + (t & 1) * 128 * G2ST, A + (mGrp + t + 2) * 128 * 256, tid);
        asm volatile("cp.async.commit_group;\n");   // empty group OK when nothing staged
    }
}

// ---------------- tensor-core attention scores (unchanged) ----------------
#define BS_STRIDE 264
#define AS_STRIDE 72
#define GEMM_SMEM ((128 * BS_STRIDE + 2 * 128 * AS_STRIDE) * 2)

__global__ __launch_bounds__(256)
void scores_mma_kernel(const __half* __restrict__ A,    // d_h1h [M][256]
                       const __half* __restrict__ Bw,   // d_Wa16 [128][256]
                       const float* __restrict__ ba1,
                       const float* __restrict__ Wa2,
                       const float* __restrict__ ba2,
                       float* __restrict__ scores) {
    extern __shared__ __align__(16) __half sm[];
    __half* Bs = sm;
    __half* As = sm + 128 * BS_STRIDE;
    __shared__ float ba1s[128];
    __shared__ float wa2s[128];

    const int tid  = threadIdx.x;
    const int warp = tid >> 5;
    const int lane = tid & 31;
    const size_t mBase = (size_t)blockIdx.x * 128;

    if (tid < 128) { ba1s[tid] = ba1[tid]; wa2s[tid] = Wa2[tid]; }

    {
        for (int i = tid; i < 4096; i += 256) {
            int row = i >> 5, seg = i & 31;
            cp16(&Bs[row * BS_STRIDE + seg * 8], Bw + (size_t)row * 256 + seg * 8);
        }
        const __half* ag = A + mBase * 256;
        for (int i = tid; i < 1024; i += 256) {
            int row = i >> 3, seg = i & 7;
            cp16(&As[row * AS_STRIDE + seg * 8], ag + (size_t)row * 256 + seg * 8);
        }
        asm volatile("cp.async.commit_group;\n");
        const __half* ag1 = A + mBase * 256 + 64;
        for (int i = tid; i < 1024; i += 256) {
            int row = i >> 3, seg = i & 7;
            cp16(&As[(128 + row) * AS_STRIDE + seg * 8], ag1 + (size_t)row * 256 + seg * 8);
        }
        asm volatile("cp.async.commit_group;\n");
    }

    float acc[16][4];
#pragma unroll
    for (int q = 0; q < 16; ++q) { acc[q][0] = acc[q][1] = acc[q][2] = acc[q][3] = 0.f; }

    for (int kc = 0; kc < 4; ++kc) {
        if (kc < 3) asm volatile("cp.async.wait_group 1;\n");
        else        asm volatile("cp.async.wait_group 0;\n");
        __syncthreads();

        const __half* as = As + (kc & 1) * 128 * AS_STRIDE;
#pragma unroll
        for (int kf = 0; kf < 4; ++kf) {
            uint32_t ra0, ra1, ra2, ra3;
            uint32_t saddrA = (uint32_t)__cvta_generic_to_shared(
                &as[(warp * 16 + (lane & 15)) * AS_STRIDE + (lane >> 4) * 8 + kf * 16]);
            asm volatile("ldmatrix.sync.aligned.m8n8.x4.shared.b16 {%0,%1,%2,%3},[%4];"
                         : "=r"(ra0), "=r"(ra1), "=r"(ra2), "=r"(ra3) : "r"(saddrA));
#pragma unroll
            for (int nb = 0; nb < 8; ++nb) {
                uint32_t rb0, rb1, rb2, rb3;
                uint32_t saddrB = (uint32_t)__cvta_generic_to_shared(
                    &Bs[(nb * 16 + ((lane >> 4) & 1) * 8 + (lane & 7)) * BS_STRIDE +
                        ((lane >> 3) & 1) * 8 + kc * 64 + kf * 16]);
                asm volatile("ldmatrix.sync.aligned.m8n8.x4.shared.b16 {%0,%1,%2,%3},[%4];"
                             : "=r"(rb0), "=r"(rb1), "=r"(rb2), "=r"(rb3) : "r"(saddrB));
                asm volatile("mma.sync.aligned.m16n8k16.row.col.f32.f16.f16.f32 "
                             "{%0,%1,%2,%3},{%4,%5,%6,%7},{%8,%9},{%0,%1,%2,%3};"
                             : "+f"(acc[nb * 2][0]), "+f"(acc[nb * 2][1]),
                               "+f"(acc[nb * 2][2]), "+f"(acc[nb * 2][3])
                             : "r"(ra0), "r"(ra1), "r"(ra2), "r"(ra3), "r"(rb0), "r"(rb1));
                asm volatile("mma.sync.aligned.m16n8k16.row.col.f32.f16.f16.f32 "
                             "{%0,%1,%2,%3},{%4,%5,%6,%7},{%8,%9},{%0,%1,%2,%3};"
                             : "+f"(acc[nb * 2 + 1][0]), "+f"(acc[nb * 2 + 1][1]),
                               "+f"(acc[nb * 2 + 1][2]), "+f"(acc[nb * 2 + 1][3])
                             : "r"(ra0), "r"(ra1), "r"(ra2), "r"(ra3), "r"(rb2), "r"(rb3));
            }
        }
        __syncthreads();

        if (kc < 2) {
            const __half* ag = A + mBase * 256 + (kc + 2) * 64;
            for (int i = tid; i < 1024; i += 256) {
                int row = i >> 3, seg = i & 7;
                cp16(&As[((kc & 1) * 128 + row) * AS_STRIDE + seg * 8],
                     ag + (size_t)row * 256 + seg * 8);
            }
            asm volatile("cp.async.commit_group;\n");
        }
    }

    const float b2 = ba2[0];
    float p0 = 0.f, p1 = 0.f;
#pragma unroll
    for (int nb = 0; nb < 8; ++nb) {
#pragma unroll
        for (int h = 0; h < 2; ++h) {
            const int q = nb * 2 + h;
            const int c0 = nb * 16 + h * 8 + (lane & 3) * 2;
            const int c1 = c0 + 1;
            p0 += tanh_fast(acc[q][0] + ba1s[c0]) * wa2s[c0]
                + tanh_fast(acc[q][1] + ba1s[c1]) * wa2s[c1];
            p1 += tanh_fast(acc[q][2] + ba1s[c0]) * wa2s[c0]
                + tanh_fast(acc[q][3] + ba1s[c1]) * wa2s[c1];
        }
    }
    p0 += __shfl_xor_sync(0xffffffffu, p0, 1);
    p0 += __shfl_xor_sync(0xffffffffu, p0, 2);
    p1 += __shfl_xor_sync(0xffffffffu, p1, 1);
    p1 += __shfl_xor_sync(0xffffffffu, p1, 2);
    if ((lane & 3) == 0) {
        const size_t row = mBase + warp * 16 + (lane >> 2);
        scores[row]     = p0 + b2;
        scores[row + 8] = p1 + b2;
    }
}

// ---------------- softmax over T + context + LN head + output (unchanged) ----------
__global__ __launch_bounds__(256) void finish_kernel(const float* __restrict__ Wf1,
                                                     const float* __restrict__ bf1,
                                                     const float* __restrict__ g2,
                                                     const float* __restrict__ b2v,
                                                     const float* __restrict__ Wf2,
                                                     const float* __restrict__ bf2,
                                                     float* __restrict__ out) {
    const int b = blockIdx.x;
    const int tid = threadIdx.x;
    __shared__ float attn[256];
    __shared__ __align__(16) float ctx[256];
    __shared__ float zs[128];
    __shared__ float red[8];

    float s = d_scores[b * TT + tid];

    float v = s;
#pragma unroll
    for (int o = 16; o; o >>= 1) v = fmaxf(v, __shfl_xor_sync(0xffffffffu, v, o));
    if ((tid & 31) == 0) red[tid >> 5] = v;
    __syncthreads();
    float mx = fmaxf(fmaxf(fmaxf(red[0], red[1]), fmaxf(red[2], red[3])),
                     fmaxf(fmaxf(red[4], red[5]), fmaxf(red[6], red[7])));
    float e = __expf(s - mx);
    float v2 = e;
#pragma unroll
    for (int o = 16; o; o >>= 1) v2 += __shfl_xor_sync(0xffffffffu, v2, o);
    __syncthreads();
    if ((tid & 31) == 0) red[tid >> 5] = v2;
    __syncthreads();
    float sum = red[0] + red[1] + red[2] + red[3] + red[4] + red[5] + red[6] + red[7];
    attn[tid] = e / sum;
    __syncthreads();

    float acc = 0.f;
    const __half* hb = d_h1h + (size_t)b * TT * 256;
    for (int t = 0; t < TT; ++t) acc += __half2float(hb[t * 256 + tid]) * attn[t];
    ctx[tid] = acc;
    __syncthreads();

    float z = 0.f;
    if (tid < 128) {
        z = bf1[tid];
        const float4* wf = reinterpret_cast<const float4*>(Wf1 + (size_t)tid * 256);
        const float4* cx = reinterpret_cast<const float4*>(ctx);
#pragma unroll 8
        for (int k4 = 0; k4 < 64; ++k4) {
            float4 w = wf[k4];
            float4 c4 = cx[k4];
            z += w.x * c4.x + w.y * c4.y + w.z * c4.z + w.w * c4.w;
        }
        float s1 = z, s2 = z * z;
#pragma unroll
        for (int o = 16; o; o >>= 1) {
            s1 += __shfl_xor_sync(0xffffffffu, s1, o);
            s2 += __shfl_xor_sync(0xffffffffu, s2, o);
        }
        if ((tid & 31) == 0) { red[tid >> 5] = s1; red[4 + (tid >> 5)] = s2; }
    }
    __syncthreads();
    if (tid < 128) {
        float mu = (red[0] + red[1] + red[2] + red[3]) * (1.f / 128.f);
        float ms = (red[4] + red[5] + red[6] + red[7]) * (1.f / 128.f);
        float var = ms - mu * mu;
        float zn = (z - mu) * rsqrtf(var + LN_EPS) * g2[tid] + b2v[tid];
        zs[tid] = fmaxf(zn, 0.f);
    }
    __syncthreads();
    if (tid < 5) {
        float y = bf2[tid];
        const float* w = Wf2 + tid * 128;
#pragma unroll 8
        for (int k = 0; k < 128; ++k) y += w[k] * zs[k];
        out[b * 5 + tid] = y;
    }
}

// ---------------- launch ----------------
extern "C" void kernel_launch(void* const* d_in, const int* in_sizes, int n_in,
                              void* d_out, int out_size) {
    const float* x     = (const float*)d_in[0];
    const float* ln_g  = (const float*)d_in[1];
    const float* ln_b  = (const float*)d_in[2];
    const float* Wih0  = (const float*)d_in[3];
    const float* Whh0  = (const float*)d_in[4];
    const float* bih0  = (const float*)d_in[5];
    const float* bhh0  = (const float*)d_in[6];
    const float* Wih1  = (const float*)d_in[7];
    const float* Whh1  = (const float*)d_in[8];
    const float* bih1  = (const float*)d_in[9];
    const float* bhh1  = (const float*)d_in[10];
    const float* Wa1   = (const float*)d_in[11];
    const float* ba1   = (const float*)d_in[12];
    const float* Wa2   = (const float*)d_in[13];
    const float* ba2   = (const float*)d_in[14];
    const float* Wf1   = (const float*)d_in[15];
    const float* bf1   = (const float*)d_in[16];
    const float* ln2_g = (const float*)d_in[17];
    const float* ln2_b = (const float*)d_in[18];
    const float* Wf2   = (const float*)d_in[19];
    const float* bf2   = (const float*)d_in[20];
    float* out = (float*)d_out;

    float  *p_xn, *p_b0, *p_b1, *p_sc;
    __half *p_h0h, *p_h1h, *p_xph, *p_W16, *p_W0cat, *p_Whh1h, *p_Wa16;
    cudaGetSymbolAddress((void**)&p_xn,    d_xn);
    cudaGetSymbolAddress((void**)&p_h0h,   d_h0h);
    cudaGetSymbolAddress((void**)&p_h1h,   d_h1h);
    cudaGetSymbolAddress((void**)&p_xph,   d_xph);
    cudaGetSymbolAddress((void**)&p_b0,    d_b0);
    cudaGetSymbolAddress((void**)&p_b1,    d_b1);
    cudaGetSymbolAddress((void**)&p_W16,   d_W16);
    cudaGetSymbolAddress((void**)&p_W0cat, d_W0cat);
    cudaGetSymbolAddress((void**)&p_Whh1h, d_Whh1h);
    cudaGetSymbolAddress((void**)&p_Wa16,  d_Wa16);
    cudaGetSymbolAddress((void**)&p_sc,    d_scores);

    cudaFuncSetAttribute(xp_gemm2_kernel,
                         cudaFuncAttributeMaxDynamicSharedMemorySize, GEMM2_SMEM);
    cudaFuncSetAttribute(scores_mma_kernel,
                         cudaFuncAttributeMaxDynamicSharedMemorySize, GEMM_SMEM);
    cudaFuncSetAttribute(lstm_tc2_kernel<0>,
                         cudaFuncAttributeMaxDynamicSharedMemorySize, LSTM0_SMEM);
    cudaFuncSetAttribute(lstm_tc2_kernel<1>,
                         cudaFuncAttributeMaxDynamicSharedMemorySize, LSTM1_SMEM);

    pack_kernel<<<512, 512>>>(Wih0, Whh0, bih0, bhh0, Wih1, Whh1, bih1, bhh1, Wa1);
    ln_kernel<<<(BSZ * TT + 255) / 256, 256>>>(x, ln_g, ln_b);

    dim3 gl(BSZ / 16, 2);
    lstm_tc2_kernel<0><<<gl, 512, LSTM0_SMEM>>>(p_xn, nullptr, p_W0cat, p_b0, p_h0h);

    dim3 gg(8, (BSZ * TT) / (128 * 16));    // 8 n-tiles x 128 m-groups
    xp_gemm2_kernel<<<gg, 512, GEMM2_SMEM>>>(p_h0h, p_W16, p_xph);

    lstm_tc2_kernel<1><<<gl, 512, LSTM1_SMEM>>>(nullptr, p_xph, p_Whh1h, p_b1, p_h1h);

    scores_mma_kernel<<<(BSZ * TT) / 128, 256, GEMM_SMEM>>>(p_h1h, p_Wa16, ba1, Wa2, ba2, p_sc);
    finish_kernel<<<BSZ, 256>>>(Wf1, bf1, ln2_g, ln2_b, Wf2, bf2, out);
}

// round 13
// speedup vs baseline: 1.0276x; 1.0276x over previous
#include <cuda_runtime.h>
#include <cuda_fp16.h>
#include <cstdint>
#include <math.h>

#define BSZ 1024
#define TT  256
#define DIN0 6
#define HH  128
#define LN_EPS 1e-5f

// ---------------- scratch (device globals; no allocations allowed) ----------------
__device__ float  d_xn[BSZ * TT * DIN0];             // layer-normed input
__device__ __half d_h0h[(size_t)BSZ * TT * 256];     // layer0 output (fp16)
__device__ __half d_h1h[(size_t)BSZ * TT * 256];     // layer1 output (fp16)
__device__ __half d_xph[(size_t)BSZ * TT * 1024];    // layer1 pre-activations (fp16)
__device__ float  d_scores[BSZ * TT];
// packed weights.  Gate-column permutation (shuffle-free activation):
//   for unit j (0..127), gate g (0=i,1=f,2=g,3=o):
//   w=j>>3, u=j&7, nb=u>>2, uu=u&3  ->  col p = w*32 + nb*16 + (g>=2)*8 + uu*2 + (g&1)
__device__ float  d_b0[2 * 512];                     // bias, unit-major [dir][j][4] (i,f,g,o)
__device__ float  d_b1[2 * 512];
__device__ __half d_W16[1024 * 256];                 // layer1 Wih fp16 [n=dir*512+p][k]
__device__ __half d_W0cat[2 * 512 * 144];            // layer0 [Whh | Wih0 | 0pad] fp16
__device__ __half d_Whh1h[2 * 512 * 128];            // layer1 Whh fp16 [dir][p][k]
__device__ __half d_Wa16[128 * 256];                 // Wa1 fp16 [n][k] row-major

// ---------------- activation helpers ----------------
__device__ __forceinline__ float tanh_fast(float x) {
    float y;
    asm("tanh.approx.f32 %0, %1;" : "=f"(y) : "f"(x));
    return y;
}
__device__ __forceinline__ float sig_fast(float x) {
    return fmaf(0.5f, tanh_fast(0.5f * x), 0.5f);
}

__device__ __forceinline__ void cp16(void* smem_dst, const void* gsrc) {
    uint32_t s = (uint32_t)__cvta_generic_to_shared(smem_dst);
    asm volatile("cp.async.cg.shared.global [%0], [%1], 16;\n" :: "r"(s), "l"(gsrc));
}
__device__ __forceinline__ void cp8(void* smem_dst, const void* gsrc) {
    uint32_t s = (uint32_t)__cvta_generic_to_shared(smem_dst);
    asm volatile("cp.async.ca.shared.global [%0], [%1], 8;\n" :: "r"(s), "l"(gsrc));
}

// ---------------- weight packing (new gate-column permutation) ----------------
__global__ void pack_kernel(const float* __restrict__ Wih0, const float* __restrict__ Whh0,
                            const float* __restrict__ bih0, const float* __restrict__ bhh0,
                            const float* __restrict__ Wih1, const float* __restrict__ Whh1,
                            const float* __restrict__ bih1, const float* __restrict__ bhh1,
                            const float* __restrict__ Wa1) {
    int i = blockIdx.x * blockDim.x + threadIdx.x;
    const int total = 2 * 256 * 512;
    for (; i < total; i += gridDim.x * blockDim.x) {
        int d   = i / (256 * 512);
        int rem = i - d * (256 * 512);
        int k   = rem >> 9;          // 0..255
        int p   = rem & 511;         // packed gate column
        // invert the permutation: p -> (j, g)
        int w  = p >> 5;
        int r5 = p & 31;
        int nb = r5 >> 4;
        int r4 = r5 & 15;
        int hh = r4 >> 3;
        int r3 = r4 & 7;
        int uu = r3 >> 1;
        int gl = r3 & 1;
        int j  = w * 8 + nb * 4 + uu;
        int g  = hh * 2 + gl;
        int gi = g * 128 + j;        // PyTorch gate row (i,f,g,o blocks of 128)

        d_W16[(size_t)(d * 512 + p) * 256 + k] = __float2half(Wih1[(d * 512 + gi) * 256 + k]);
        if (i < 128 * 256)
            d_Wa16[i] = __float2half(Wa1[i]);
        if (k < 128)
            d_Whh1h[(d * 512 + p) * 128 + k] = __float2half(Whh1[(d * 512 + gi) * 128 + k]);
        if (k < 144) {
            float v;
            if (k < 128)        v = Whh0[(d * 512 + gi) * 128 + k];
            else if (k < 128 + DIN0) v = Wih0[(d * 512 + gi) * DIN0 + (k - 128)];
            else                v = 0.f;
            d_W0cat[(d * 512 + p) * 144 + k] = __float2half(v);
        }
        if (k == 0) {       // bias stays unit-major: [dir][j][g]
            d_b0[d * 512 + j * 4 + g] = bih0[d * 512 + gi] + bhh0[d * 512 + gi];
            d_b1[d * 512 + j * 4 + g] = bih1[d * 512 + gi] + bhh1[d * 512 + gi];
        }
    }
}

// ---------------- input layernorm (over last dim = 6) ----------------
__global__ void ln_kernel(const float* __restrict__ x,
                          const float* __restrict__ g,
                          const float* __restrict__ b) {
    int row = blockIdx.x * blockDim.x + threadIdx.x;
    if (row >= BSZ * TT) return;
    const float* xr = x + (size_t)row * DIN0;
    float v[DIN0];
    float mu = 0.f;
#pragma unroll
    for (int k = 0; k < DIN0; ++k) { v[k] = xr[k]; mu += v[k]; }
    mu *= (1.f / DIN0);
    float var = 0.f;
#pragma unroll
    for (int k = 0; k < DIN0; ++k) { float d = v[k] - mu; var += d * d; }
    var *= (1.f / DIN0);
    float inv = rsqrtf(var + LN_EPS);
#pragma unroll
    for (int k = 0; k < DIN0; ++k)
        d_xn[(size_t)row * DIN0 + k] = (v[k] - mu) * inv * g[k] + b[k];
}

// ---------------- tensor-core BiLSTM recurrence v3 ----------------
// Shuffle-free: thread (warp w, lane) owns units jq = w*8 + nb*4 + (lane&3), nb=0,1,
// rows (lane>>2) and +8.  acc[nb*2] holds (i,f), acc[nb*2+1] holds (g,o).
// MMAs issued nb-outer so activation(nb0) overlaps nb1's tensor work.
#define XPST 516

template <int LAYER>
__global__ __launch_bounds__(512, 1)
void lstm_tc2_kernel(const float* __restrict__ xn,     // L0 input [B][T][6]
                     const __half* __restrict__ xph,   // L1 input xp [B*T][1024]
                     const __half* __restrict__ Wmat,  // L0: [2][512][144]; L1: [2][512][128]
                     const float* __restrict__ biasp,  // [2][512] unit-major
                     __half* __restrict__ hout) {      // [B][T][256] fp16
    constexpr int KDIM = (LAYER == 0) ? 144 : 128;
    constexpr int KC   = KDIM / 16;
    constexpr int BSTX = (LAYER == 0) ? 152 : 136;

    extern __shared__ __align__(16) unsigned char smraw[];
    __half* Bs = reinterpret_cast<__half*>(smraw);     // [512][BSTX]
    __half* Hs = Bs + 512 * BSTX;                      // [2][16][BSTX]
    __half* Xp = Hs + 2 * 16 * BSTX;                   // [2][16][XPST] (L1 only)

    const int tid  = threadIdx.x;
    const int warp = tid >> 5;
    const int lane = tid & 31;
    const int dir  = blockIdx.y;
    const int bb0  = blockIdx.x * 16;
    const int j    = tid & 127;
    const int rg   = tid >> 7;
    const int nb0c = warp * 32;
    const int half = dir * 128;

    {
        const __half* src = Wmat + (size_t)dir * 512 * KDIM;
        constexpr int CH = KDIM / 8;
        for (int i = tid; i < 512 * CH; i += 512) {
            int n = i / CH, seg = i - n * CH;
            cp16(&Bs[n * BSTX + seg * 8], src + (size_t)n * KDIM + seg * 8);
        }
    }
    for (int i = tid; i < 2 * 16 * BSTX; i += 512) Hs[i] = __float2half(0.f);

    {
        const int tt0 = dir ? (TT - 1) : 0;
        if (LAYER == 0) {
            if (tid < 16 * DIN0) {
                int r = tid / DIN0, k = tid - r * DIN0;
                Hs[r * BSTX + 128 + k] =
                    __float2half(xn[((size_t)(bb0 + r) * TT + tt0) * DIN0 + k]);
            }
        } else {
#pragma unroll
            for (int rr = 0; rr < 4; ++rr) {
                int row = rg * 4 + rr;
                cp8(&Xp[row * XPST + j * 4],
                    &xph[((size_t)(bb0 + row) * TT + tt0) * 1024 + half * 4 + j * 4]);
            }
            asm volatile("cp.async.commit_group;\n");
        }
    }
    asm volatile("cp.async.wait_group 0;\n" ::: "memory");

    // per-thread unit bias (unit-major): units w*8 + nb*4 + uu
    const int uu = lane & 3;
    const int r0 = lane >> 2;
    float4 bq[2];
#pragma unroll
    for (int nb = 0; nb < 2; ++nb)
        bq[nb] = reinterpret_cast<const float4*>(biasp + dir * 512)[warp * 8 + nb * 4 + uu];

    float c[4] = {0.f, 0.f, 0.f, 0.f};   // cell = nb*2 + rowhalf
    __syncthreads();

    for (int s = 0; s < TT; ++s) {
        const int cur = s & 1, nxt = (s + 1) & 1;

        if (s + 1 < TT) {
            const int ttn = dir ? (TT - 2 - s) : (s + 1);
            if (LAYER == 0) {
                if (tid < 16 * DIN0) {
                    int r = tid / DIN0, k = tid - r * DIN0;
                    Hs[nxt * 16 * BSTX + r * BSTX + 128 + k] =
                        __float2half(xn[((size_t)(bb0 + r) * TT + ttn) * DIN0 + k]);
                }
            } else {
#pragma unroll
                for (int rr = 0; rr < 4; ++rr) {
                    int row = rg * 4 + rr;
                    cp8(&Xp[nxt * 16 * XPST + row * XPST + j * 4],
                        &xph[((size_t)(bb0 + row) * TT + ttn) * 1024 + half * 4 + j * 4]);
                }
            }
        }
        if (LAYER == 1) asm volatile("cp.async.commit_group;\n");

        if (s > 0) {
            const int tts = dir ? (TT - s) : (s - 1);
#pragma unroll
            for (int rr = 0; rr < 4; ++rr) {
                int row = rg * 4 + rr;
                hout[((size_t)(bb0 + row) * TT + tts) * 256 + half + j] =
                    Hs[cur * 16 * BSTX + row * BSTX + j];
            }
        }

        // ---- A fragments (cached once) ----
        const __half* hsc = Hs + cur * 16 * BSTX;
        uint32_t raf[KC][4];
#pragma unroll
        for (int kc = 0; kc < KC; ++kc) {
            uint32_t sa = (uint32_t)__cvta_generic_to_shared(
                &hsc[(lane & 15) * BSTX + (lane >> 4) * 8 + kc * 16]);
            asm volatile("ldmatrix.sync.aligned.m8n8.x4.shared.b16 {%0,%1,%2,%3},[%4];"
                         : "=r"(raf[kc][0]), "=r"(raf[kc][1]),
                           "=r"(raf[kc][2]), "=r"(raf[kc][3]) : "r"(sa));
        }

        // ---- MMAs nb-outer ----
        float acc[4][4];
#pragma unroll
        for (int q = 0; q < 4; ++q) { acc[q][0] = acc[q][1] = acc[q][2] = acc[q][3] = 0.f; }
#pragma unroll
        for (int nb = 0; nb < 2; ++nb) {
#pragma unroll
            for (int kc = 0; kc < KC; ++kc) {
                uint32_t rb0, rb1, rb2, rb3;
                uint32_t sb = (uint32_t)__cvta_generic_to_shared(
                    &Bs[(nb0c + nb * 16 + ((lane >> 4) & 1) * 8 + (lane & 7)) * BSTX +
                        ((lane >> 3) & 1) * 8 + kc * 16]);
                asm volatile("ldmatrix.sync.aligned.m8n8.x4.shared.b16 {%0,%1,%2,%3},[%4];"
                             : "=r"(rb0), "=r"(rb1), "=r"(rb2), "=r"(rb3) : "r"(sb));
                asm volatile("mma.sync.aligned.m16n8k16.row.col.f32.f16.f16.f32 "
                             "{%0,%1,%2,%3},{%4,%5,%6,%7},{%8,%9},{%0,%1,%2,%3};"
                             : "+f"(acc[nb * 2][0]), "+f"(acc[nb * 2][1]),
                               "+f"(acc[nb * 2][2]), "+f"(acc[nb * 2][3])
                             : "r"(raf[kc][0]), "r"(raf[kc][1]), "r"(raf[kc][2]), "r"(raf[kc][3]),
                               "r"(rb0), "r"(rb1));
                asm volatile("mma.sync.aligned.m16n8k16.row.col.f32.f16.f16.f32 "
                             "{%0,%1,%2,%3},{%4,%5,%6,%7},{%8,%9},{%0,%1,%2,%3};"
                             : "+f"(acc[nb * 2 + 1][0]), "+f"(acc[nb * 2 + 1][1]),
                               "+f"(acc[nb * 2 + 1][2]), "+f"(acc[nb * 2 + 1][3])
                             : "r"(raf[kc][0]), "r"(raf[kc][1]), "r"(raf[kc][2]), "r"(raf[kc][3]),
                               "r"(rb2), "r"(rb3));
            }
        }

        // ---- activation (shuffle-free; nb0 overlaps nb1's tensor drain) ----
        __half* hsn = Hs + nxt * 16 * BSTX;
#pragma unroll
        for (int nb = 0; nb < 2; ++nb) {
            const int jq = warp * 8 + nb * 4 + uu;
            const int pif = warp * 32 + nb * 16 + uu * 2;   // xp cols (i,f); (g,o) at +8
#pragma unroll
            for (int rh = 0; rh < 2; ++rh) {
                const int row = r0 + rh * 8;
                float ai = acc[nb * 2][rh * 2 + 0] + bq[nb].x;
                float af = acc[nb * 2][rh * 2 + 1] + bq[nb].y;
                float ag = acc[nb * 2 + 1][rh * 2 + 0] + bq[nb].z;
                float ao = acc[nb * 2 + 1][rh * 2 + 1] + bq[nb].w;
                if (LAYER == 1) {
                    const __half2 xif = *reinterpret_cast<const __half2*>(
                        &Xp[cur * 16 * XPST + row * XPST + pif]);
                    const __half2 xgo = *reinterpret_cast<const __half2*>(
                        &Xp[cur * 16 * XPST + row * XPST + pif + 8]);
                    ai += __low2float(xif);  af += __high2float(xif);
                    ag += __low2float(xgo);  ao += __high2float(xgo);
                }
                float ii = sig_fast(ai);
                float ff = sig_fast(af);
                float G  = tanh_fast(ag);
                float oo = sig_fast(ao);
                const int cell = nb * 2 + rh;
                c[cell] = ff * c[cell] + ii * G;
                float hv = oo * tanh_fast(c[cell]);
                hsn[row * BSTX + jq] = __float2half(hv);
            }
        }

        if (LAYER == 1) asm volatile("cp.async.wait_group 0;\n" ::: "memory");
        __syncthreads();
    }

    {
        const int tts = dir ? 0 : (TT - 1);
#pragma unroll
        for (int rr = 0; rr < 4; ++rr) {
            int row = rg * 4 + rr;
            hout[((size_t)(bb0 + row) * TT + tts) * 256 + half + j] =
                Hs[((TT) & 1) * 16 * BSTX + row * BSTX + j];
        }
    }
}

#define LSTM0_SMEM ((512 * 152 + 2 * 16 * 152) * 2)
#define LSTM1_SMEM ((512 * 136 + 2 * 16 * 136) * 2 + 2 * 16 * XPST * 2)

// ================= xp GEMM (R11 best config: 256 thr, warp tile 32M x 64N) ==========
#define G2ST 264
#define GEMM2_SMEM (3 * 128 * G2ST * 2)   // 202752 bytes

__device__ __forceinline__ void g2_stage(__half* dst, const __half* g, int tid) {
#pragma unroll
    for (int it = 0; it < 16; ++it) {
        int i = tid + it * 256;
        int row = i >> 5, seg = i & 31;
        cp16(&dst[row * G2ST + seg * 8], g + (size_t)row * 256 + seg * 8);
    }
}

__global__ __launch_bounds__(256, 1)
void xp_gemm2_kernel(const __half* __restrict__ A,   // [M][256]
                     const __half* __restrict__ Bw,  // [1024][256]
                     __half* __restrict__ C) {       // [M][1024] fp16
    extern __shared__ __align__(16) __half sm[];
    __half* Bs = sm;                   // [128][G2ST]
    __half* As = sm + 128 * G2ST;      // [2][128][G2ST]

    const int tid  = threadIdx.x;
    const int warp = tid >> 5;
    const int lane = tid & 31;
    const int warpM = warp >> 1;       // 0..3 -> m offset *32
    const int warpN = warp & 1;        // 0..1 -> n offset *64
    const int    nBase = blockIdx.x * 128;
    const size_t mGrp  = (size_t)blockIdx.y * 16;    // first m-subtile

    g2_stage(Bs, Bw + (size_t)nBase * 256, tid);
    g2_stage(As, A + mGrp * 128 * 256, tid);
    asm volatile("cp.async.commit_group;\n");
    g2_stage(As + 128 * G2ST, A + (mGrp + 1) * 128 * 256, tid);
    asm volatile("cp.async.commit_group;\n");

    for (int t = 0; t < 16; ++t) {
        if (t < 15) asm volatile("cp.async.wait_group 1;\n");
        else        asm volatile("cp.async.wait_group 0;\n");
        __syncthreads();

        const __half* as = As + (t & 1) * 128 * G2ST;
        float acc[16][4];
#pragma unroll
        for (int q = 0; q < 16; ++q) { acc[q][0] = acc[q][1] = acc[q][2] = acc[q][3] = 0.f; }

#pragma unroll
        for (int kf = 0; kf < 16; ++kf) {
            uint32_t ra[2][4];
#pragma unroll
            for (int mf = 0; mf < 2; ++mf) {
                uint32_t saddrA = (uint32_t)__cvta_generic_to_shared(
                    &as[(warpM * 32 + mf * 16 + (lane & 15)) * G2ST +
                        (lane >> 4) * 8 + kf * 16]);
                asm volatile("ldmatrix.sync.aligned.m8n8.x4.shared.b16 {%0,%1,%2,%3},[%4];"
                             : "=r"(ra[mf][0]), "=r"(ra[mf][1]),
                               "=r"(ra[mf][2]), "=r"(ra[mf][3]) : "r"(saddrA));
            }
#pragma unroll
            for (int nb = 0; nb < 4; ++nb) {
                uint32_t rb0, rb1, rb2, rb3;
                uint32_t saddrB = (uint32_t)__cvta_generic_to_shared(
                    &Bs[(warpN * 64 + nb * 16 + ((lane >> 4) & 1) * 8 + (lane & 7)) * G2ST +
                        ((lane >> 3) & 1) * 8 + kf * 16]);
                asm volatile("ldmatrix.sync.aligned.m8n8.x4.shared.b16 {%0,%1,%2,%3},[%4];"
                             : "=r"(rb0), "=r"(rb1), "=r"(rb2), "=r"(rb3) : "r"(saddrB));
#pragma unroll
                for (int mf = 0; mf < 2; ++mf) {
                    asm volatile("mma.sync.aligned.m16n8k16.row.col.f32.f16.f16.f32 "
                                 "{%0,%1,%2,%3},{%4,%5,%6,%7},{%8,%9},{%0,%1,%2,%3};"
                                 : "+f"(acc[mf * 8 + nb * 2][0]), "+f"(acc[mf * 8 + nb * 2][1]),
                                   "+f"(acc[mf * 8 + nb * 2][2]), "+f"(acc[mf * 8 + nb * 2][3])
                                 : "r"(ra[mf][0]), "r"(ra[mf][1]), "r"(ra[mf][2]), "r"(ra[mf][3]),
                                   "r"(rb0), "r"(rb1));
                    asm volatile("mma.sync.aligned.m16n8k16.row.col.f32.f16.f16.f32 "
                                 "{%0,%1,%2,%3},{%4,%5,%6,%7},{%8,%9},{%0,%1,%2,%3};"
                                 : "+f"(acc[mf * 8 + nb * 2 + 1][0]), "+f"(acc[mf * 8 + nb * 2 + 1][1]),
                                   "+f"(acc[mf * 8 + nb * 2 + 1][2]), "+f"(acc[mf * 8 + nb * 2 + 1][3])
                                 : "r"(ra[mf][0]), "r"(ra[mf][1]), "r"(ra[mf][2]), "r"(ra[mf][3]),
                                   "r"(rb2), "r"(rb3));
                }
            }
        }

        {
            const size_t rowA = (mGrp + t) * 128 + warpM * 32 + (lane >> 2);
            const int    colA = nBase + warpN * 64 + (lane & 3) * 2;
#pragma unroll
            for (int mf = 0; mf < 2; ++mf) {
#pragma unroll
                for (int nb = 0; nb < 4; ++nb) {
#pragma unroll
                    for (int h = 0; h < 2; ++h) {
                        const int q = mf * 8 + nb * 2 + h;
                        const size_t r0 = rowA + mf * 16;
                        const int    cc = colA + nb * 16 + h * 8;
                        *reinterpret_cast<__half2*>(&C[r0 * 1024 + cc]) =
                            __floats2half2_rn(acc[q][0], acc[q][1]);
                        *reinterpret_cast<__half2*>(&C[(r0 + 8) * 1024 + cc]) =
                            __floats2half2_rn(acc[q][2], acc[q][3]);
                    }
                }
            }
        }
        __syncthreads();

        if (t + 2 < 16)
            g2_stage(As + (t & 1) * 128 * G2ST, A + (mGrp + t + 2) * 128 * 256, tid);
        asm volatile("cp.async.commit_group;\n");
    }
}

// ---------------- tensor-core attention scores (unchanged) ----------------
#define BS_STRIDE 264
#define AS_STRIDE 72
#define GEMM_SMEM ((128 * BS_STRIDE + 2 * 128 * AS_STRIDE) * 2)

__global__ __launch_bounds__(256)
void scores_mma_kernel(const __half* __restrict__ A,    // d_h1h [M][256]
                       const __half* __restrict__ Bw,   // d_Wa16 [128][256]
                       const float* __restrict__ ba1,
                       const float* __restrict__ Wa2,
                       const float* __restrict__ ba2,
                       float* __restrict__ scores) {
    extern __shared__ __align__(16) __half sm[];
    __half* Bs = sm;
    __half* As = sm + 128 * BS_STRIDE;
    __shared__ float ba1s[128];
    __shared__ float wa2s[128];

    const int tid  = threadIdx.x;
    const int warp = tid >> 5;
    const int lane = tid & 31;
    const size_t mBase = (size_t)blockIdx.x * 128;

    if (tid < 128) { ba1s[tid] = ba1[tid]; wa2s[tid] = Wa2[tid]; }

    {
        for (int i = tid; i < 4096; i += 256) {
            int row = i >> 5, seg = i & 31;
            cp16(&Bs[row * BS_STRIDE + seg * 8], Bw + (size_t)row * 256 + seg * 8);
        }
        const __half* ag = A + mBase * 256;
        for (int i = tid; i < 1024; i += 256) {
            int row = i >> 3, seg = i & 7;
            cp16(&As[row * AS_STRIDE + seg * 8], ag + (size_t)row * 256 + seg * 8);
        }
        asm volatile("cp.async.commit_group;\n");
        const __half* ag1 = A + mBase * 256 + 64;
        for (int i = tid; i < 1024; i += 256) {
            int row = i >> 3, seg = i & 7;
            cp16(&As[(128 + row) * AS_STRIDE + seg * 8], ag1 + (size_t)row * 256 + seg * 8);
        }
        asm volatile("cp.async.commit_group;\n");
    }

    float acc[16][4];
#pragma unroll
    for (int q = 0; q < 16; ++q) { acc[q][0] = acc[q][1] = acc[q][2] = acc[q][3] = 0.f; }

    for (int kc = 0; kc < 4; ++kc) {
        if (kc < 3) asm volatile("cp.async.wait_group 1;\n");
        else        asm volatile("cp.async.wait_group 0;\n");
        __syncthreads();

        const __half* as = As + (kc & 1) * 128 * AS_STRIDE;
#pragma unroll
        for (int kf = 0; kf < 4; ++kf) {
            uint32_t ra0, ra1, ra2, ra3;
            uint32_t saddrA = (uint32_t)__cvta_generic_to_shared(
                &as[(warp * 16 + (lane & 15)) * AS_STRIDE + (lane >> 4) * 8 + kf * 16]);
            asm volatile("ldmatrix.sync.aligned.m8n8.x4.shared.b16 {%0,%1,%2,%3},[%4];"
                         : "=r"(ra0), "=r"(ra1), "=r"(ra2), "=r"(ra3) : "r"(saddrA));
#pragma unroll
            for (int nb = 0; nb < 8; ++nb) {
                uint32_t rb0, rb1, rb2, rb3;
                uint32_t saddrB = (uint32_t)__cvta_generic_to_shared(
                    &Bs[(nb * 16 + ((lane >> 4) & 1) * 8 + (lane & 7)) * BS_STRIDE +
                        ((lane >> 3) & 1) * 8 + kc * 64 + kf * 16]);
                asm volatile("ldmatrix.sync.aligned.m8n8.x4.shared.b16 {%0,%1,%2,%3},[%4];"
                             : "=r"(rb0), "=r"(rb1), "=r"(rb2), "=r"(rb3) : "r"(saddrB));
                asm volatile("mma.sync.aligned.m16n8k16.row.col.f32.f16.f16.f32 "
                             "{%0,%1,%2,%3},{%4,%5,%6,%7},{%8,%9},{%0,%1,%2,%3};"
                             : "+f"(acc[nb * 2][0]), "+f"(acc[nb * 2][1]),
                               "+f"(acc[nb * 2][2]), "+f"(acc[nb * 2][3])
                             : "r"(ra0), "r"(ra1), "r"(ra2), "r"(ra3), "r"(rb0), "r"(rb1));
                asm volatile("mma.sync.aligned.m16n8k16.row.col.f32.f16.f16.f32 "
                             "{%0,%1,%2,%3},{%4,%5,%6,%7},{%8,%9},{%0,%1,%2,%3};"
                             : "+f"(acc[nb * 2 + 1][0]), "+f"(acc[nb * 2 + 1][1]),
                               "+f"(acc[nb * 2 + 1][2]), "+f"(acc[nb * 2 + 1][3])
                             : "r"(ra0), "r"(ra1), "r"(ra2), "r"(ra3), "r"(rb2), "r"(rb3));
            }
        }
        __syncthreads();

        if (kc < 2) {
            const __half* ag = A + mBase * 256 + (kc + 2) * 64;
            for (int i = tid; i < 1024; i += 256) {
                int row = i >> 3, seg = i & 7;
                cp16(&As[((kc & 1) * 128 + row) * AS_STRIDE + seg * 8],
                     ag + (size_t)row * 256 + seg * 8);
            }
            asm volatile("cp.async.commit_group;\n");
        }
    }

    const float b2 = ba2[0];
    float p0 = 0.f, p1 = 0.f;
#pragma unroll
    for (int nb = 0; nb < 8; ++nb) {
#pragma unroll
        for (int h = 0; h < 2; ++h) {
            const int q = nb * 2 + h;
            const int c0 = nb * 16 + h * 8 + (lane & 3) * 2;
            const int c1 = c0 + 1;
            p0 += tanh_fast(acc[q][0] + ba1s[c0]) * wa2s[c0]
                + tanh_fast(acc[q][1] + ba1s[c1]) * wa2s[c1];
            p1 += tanh_fast(acc[q][2] + ba1s[c0]) * wa2s[c0]
                + tanh_fast(acc[q][3] + ba1s[c1]) * wa2s[c1];
        }
    }
    p0 += __shfl_xor_sync(0xffffffffu, p0, 1);
    p0 += __shfl_xor_sync(0xffffffffu, p0, 2);
    p1 += __shfl_xor_sync(0xffffffffu, p1, 1);
    p1 += __shfl_xor_sync(0xffffffffu, p1, 2);
    if ((lane & 3) == 0) {
        const size_t row = mBase + warp * 16 + (lane >> 2);
        scores[row]     = p0 + b2;
        scores[row + 8] = p1 + b2;
    }
}

// ---------------- softmax over T + context + LN head + output (unchanged) ----------
__global__ __launch_bounds__(256) void finish_kernel(const float* __restrict__ Wf1,
                                                     const float* __restrict__ bf1,
                                                     const float* __restrict__ g2,
                                                     const float* __restrict__ b2v,
                                                     const float* __restrict__ Wf2,
                                                     const float* __restrict__ bf2,
                                                     float* __restrict__ out) {
    const int b = blockIdx.x;
    const int tid = threadIdx.x;
    __shared__ float attn[256];
    __shared__ __align__(16) float ctx[256];
    __shared__ float zs[128];
    __shared__ float red[8];

    float s = d_scores[b * TT + tid];

    float v = s;
#pragma unroll
    for (int o = 16; o; o >>= 1) v = fmaxf(v, __shfl_xor_sync(0xffffffffu, v, o));
    if ((tid & 31) == 0) red[tid >> 5] = v;
    __syncthreads();
    float mx = fmaxf(fmaxf(fmaxf(red[0], red[1]), fmaxf(red[2], red[3])),
                     fmaxf(fmaxf(red[4], red[5]), fmaxf(red[6], red[7])));
    float e = __expf(s - mx);
    float v2 = e;
#pragma unroll
    for (int o = 16; o; o >>= 1) v2 += __shfl_xor_sync(0xffffffffu, v2, o);
    __syncthreads();
    if ((tid & 31) == 0) red[tid >> 5] = v2;
    __syncthreads();
    float sum = red[0] + red[1] + red[2] + red[3] + red[4] + red[5] + red[6] + red[7];
    attn[tid] = e / sum;
    __syncthreads();

    float acc = 0.f;
    const __half* hb = d_h1h + (size_t)b * TT * 256;
    for (int t = 0; t < TT; ++t) acc += __half2float(hb[t * 256 + tid]) * attn[t];
    ctx[tid] = acc;
    __syncthreads();

    float z = 0.f;
    if (tid < 128) {
        z = bf1[tid];
        const float4* wf = reinterpret_cast<const float4*>(Wf1 + (size_t)tid * 256);
        const float4* cx = reinterpret_cast<const float4*>(ctx);
#pragma unroll 8
        for (int k4 = 0; k4 < 64; ++k4) {
            float4 w = wf[k4];
            float4 c4 = cx[k4];
            z += w.x * c4.x + w.y * c4.y + w.z * c4.z + w.w * c4.w;
        }
        float s1 = z, s2 = z * z;
#pragma unroll
        for (int o = 16; o; o >>= 1) {
            s1 += __shfl_xor_sync(0xffffffffu, s1, o);
            s2 += __shfl_xor_sync(0xffffffffu, s2, o);
        }
        if ((tid & 31) == 0) { red[tid >> 5] = s1; red[4 + (tid >> 5)] = s2; }
    }
    __syncthreads();
    if (tid < 128) {
        float mu = (red[0] + red[1] + red[2] + red[3]) * (1.f / 128.f);
        float ms = (red[4] + red[5] + red[6] + red[7]) * (1.f / 128.f);
        float var = ms - mu * mu;
        float zn = (z - mu) * rsqrtf(var + LN_EPS) * g2[tid] + b2v[tid];
        zs[tid] = fmaxf(zn, 0.f);
    }
    __syncthreads();
    if (tid < 5) {
        float y = bf2[tid];
        const float* w = Wf2 + tid * 128;
#pragma unroll 8
        for (int k = 0; k < 128; ++k) y += w[k] * zs[k];
        out[b * 5 + tid] = y;
    }
}

// ---------------- launch ----------------
extern "C" void kernel_launch(void* const* d_in, const int* in_sizes, int n_in,
                              void* d_out, int out_size) {
    const float* x     = (const float*)d_in[0];
    const float* ln_g  = (const float*)d_in[1];
    const float* ln_b  = (const float*)d_in[2];
    const float* Wih0  = (const float*)d_in[3];
    const float* Whh0  = (const float*)d_in[4];
    const float* bih0  = (const float*)d_in[5];
    const float* bhh0  = (const float*)d_in[6];
    const float* Wih1  = (const float*)d_in[7];
    const float* Whh1  = (const float*)d_in[8];
    const float* bih1  = (const float*)d_in[9];
    const float* bhh1  = (const float*)d_in[10];
    const float* Wa1   = (const float*)d_in[11];
    const float* ba1   = (const float*)d_in[12];
    const float* Wa2   = (const float*)d_in[13];
    const float* ba2   = (const float*)d_in[14];
    const float* Wf1   = (const float*)d_in[15];
    const float* bf1   = (const float*)d_in[16];
    const float* ln2_g = (const float*)d_in[17];
    const float* ln2_b = (const float*)d_in[18];
    const float* Wf2   = (const float*)d_in[19];
    const float* bf2   = (const float*)d_in[20];
    float* out = (float*)d_out;

    float  *p_xn, *p_b0, *p_b1, *p_sc;
    __half *p_h0h, *p_h1h, *p_xph, *p_W16, *p_W0cat, *p_Whh1h, *p_Wa16;
    cudaGetSymbolAddress((void**)&p_xn,    d_xn);
    cudaGetSymbolAddress((void**)&p_h0h,   d_h0h);
    cudaGetSymbolAddress((void**)&p_h1h,   d_h1h);
    cudaGetSymbolAddress((void**)&p_xph,   d_xph);
    cudaGetSymbolAddress((void**)&p_b0,    d_b0);
    cudaGetSymbolAddress((void**)&p_b1,    d_b1);
    cudaGetSymbolAddress((void**)&p_W16,   d_W16);
    cudaGetSymbolAddress((void**)&p_W0cat, d_W0cat);
    cudaGetSymbolAddress((void**)&p_Whh1h, d_Whh1h);
    cudaGetSymbolAddress((void**)&p_Wa16,  d_Wa16);
    cudaGetSymbolAddress((void**)&p_sc,    d_scores);

    cudaFuncSetAttribute(xp_gemm2_kernel,
                         cudaFuncAttributeMaxDynamicSharedMemorySize, GEMM2_SMEM);
    cudaFuncSetAttribute(scores_mma_kernel,
                         cudaFuncAttributeMaxDynamicSharedMemorySize, GEMM_SMEM);
    cudaFuncSetAttribute(lstm_tc2_kernel<0>,
                         cudaFuncAttributeMaxDynamicSharedMemorySize, LSTM0_SMEM);
    cudaFuncSetAttribute(lstm_tc2_kernel<1>,
                         cudaFuncAttributeMaxDynamicSharedMemorySize, LSTM1_SMEM);

    pack_kernel<<<512, 512>>>(Wih0, Whh0, bih0, bhh0, Wih1, Whh1, bih1, bhh1, Wa1);
    ln_kernel<<<(BSZ * TT + 255) / 256, 256>>>(x, ln_g, ln_b);

    dim3 gl(BSZ / 16, 2);
    lstm_tc2_kernel<0><<<gl, 512, LSTM0_SMEM>>>(p_xn, nullptr, p_W0cat, p_b0, p_h0h);

    dim3 gg(8, (BSZ * TT) / (128 * 16));    // 8 n-tiles x 128 m-groups
    xp_gemm2_kernel<<<gg, 256, GEMM2_SMEM>>>(p_h0h, p_W16, p_xph);

    lstm_tc2_kernel<1><<<gl, 512, LSTM1_SMEM>>>(nullptr, p_xph, p_Whh1h, p_b1, p_h1h);

    scores_mma_kernel<<<(BSZ * TT) / 128, 256, GEMM_SMEM>>>(p_h1h, p_Wa16, ba1, Wa2, ba2, p_sc);
    finish_kernel<<<BSZ, 256>>>(Wf1, bf1, ln2_g, ln2_b, Wf2, bf2, out);
}

// round 14
// speedup vs baseline: 1.1896x; 1.1577x over previous
#include <cuda_runtime.h>
#include <cuda_fp16.h>
#include <cstdint>
#include <math.h>

#define BSZ 1024
#define TT  256
#define DIN0 6
#define HH  128
#define LN_EPS 1e-5f

// ---------------- scratch (device globals; no allocations allowed) ----------------
__device__ float  d_xn[BSZ * TT * DIN0];             // layer-normed input
__device__ __half d_h0h[(size_t)BSZ * TT * 256];     // layer0 output (fp16)
__device__ __half d_h1h[(size_t)BSZ * TT * 256];     // layer1 output (fp16)
__device__ __half d_xph[(size_t)BSZ * TT * 1024];    // layer1 pre-activations (fp16)
__device__ float  d_scores[BSZ * TT];
// packed weights.  Gate-column permutation (shuffle-free activation):
//   for unit j (0..127), gate g (0=i,1=f,2=g,3=o):
//   w=j>>3, u=j&7, nb=u>>2, uu=u&3  ->  col p = w*32 + nb*16 + (g>=2)*8 + uu*2 + (g&1)
__device__ float  d_b0[2 * 512];                     // bias, unit-major [dir][j][4] (i,f,g,o)
__device__ float  d_b1[2 * 512];
__device__ __half d_W16[1024 * 256];                 // layer1 Wih fp16 [n=dir*512+p][k]
__device__ __half d_W0cat[2 * 512 * 144];            // layer0 [Whh | Wih0 | 0pad] fp16
__device__ __half d_Whh1h[2 * 512 * 128];            // layer1 Whh fp16 [dir][p][k]
__device__ __half d_Wa16[128 * 256];                 // Wa1 fp16 [n][k] row-major

// ---------------- activation helpers ----------------
__device__ __forceinline__ float tanh_fast(float x) {
    float y;
    asm("tanh.approx.f32 %0, %1;" : "=f"(y) : "f"(x));
    return y;
}
__device__ __forceinline__ float sig_fast(float x) {
    return fmaf(0.5f, tanh_fast(0.5f * x), 0.5f);
}

__device__ __forceinline__ void cp16(void* smem_dst, const void* gsrc) {
    uint32_t s = (uint32_t)__cvta_generic_to_shared(smem_dst);
    asm volatile("cp.async.cg.shared.global [%0], [%1], 16;\n" :: "r"(s), "l"(gsrc));
}
__device__ __forceinline__ void cp8(void* smem_dst, const void* gsrc) {
    uint32_t s = (uint32_t)__cvta_generic_to_shared(smem_dst);
    asm volatile("cp.async.ca.shared.global [%0], [%1], 8;\n" :: "r"(s), "l"(gsrc));
}

// ---------------- weight packing (gate-column permutation) ----------------
__global__ void pack_kernel(const float* __restrict__ Wih0, const float* __restrict__ Whh0,
                            const float* __restrict__ bih0, const float* __restrict__ bhh0,
                            const float* __restrict__ Wih1, const float* __restrict__ Whh1,
                            const float* __restrict__ bih1, const float* __restrict__ bhh1,
                            const float* __restrict__ Wa1) {
    int i = blockIdx.x * blockDim.x + threadIdx.x;
    const int total = 2 * 256 * 512;
    for (; i < total; i += gridDim.x * blockDim.x) {
        int d   = i / (256 * 512);
        int rem = i - d * (256 * 512);
        int k   = rem >> 9;          // 0..255
        int p   = rem & 511;         // packed gate column
        int w  = p >> 5;
        int r5 = p & 31;
        int nb = r5 >> 4;
        int r4 = r5 & 15;
        int hh = r4 >> 3;
        int r3 = r4 & 7;
        int uu = r3 >> 1;
        int gl = r3 & 1;
        int j  = w * 8 + nb * 4 + uu;
        int g  = hh * 2 + gl;
        int gi = g * 128 + j;        // PyTorch gate row (i,f,g,o blocks of 128)

        d_W16[(size_t)(d * 512 + p) * 256 + k] = __float2half(Wih1[(d * 512 + gi) * 256 + k]);
        if (i < 128 * 256)
            d_Wa16[i] = __float2half(Wa1[i]);
        if (k < 128)
            d_Whh1h[(d * 512 + p) * 128 + k] = __float2half(Whh1[(d * 512 + gi) * 128 + k]);
        if (k < 144) {
            float v;
            if (k < 128)        v = Whh0[(d * 512 + gi) * 128 + k];
            else if (k < 128 + DIN0) v = Wih0[(d * 512 + gi) * DIN0 + (k - 128)];
            else                v = 0.f;
            d_W0cat[(d * 512 + p) * 144 + k] = __float2half(v);
        }
        if (k == 0) {
            d_b0[d * 512 + j * 4 + g] = bih0[d * 512 + gi] + bhh0[d * 512 + gi];
            d_b1[d * 512 + j * 4 + g] = bih1[d * 512 + gi] + bhh1[d * 512 + gi];
        }
    }
}

// ---------------- input layernorm (over last dim = 6) ----------------
__global__ void ln_kernel(const float* __restrict__ x,
                          const float* __restrict__ g,
                          const float* __restrict__ b) {
    int row = blockIdx.x * blockDim.x + threadIdx.x;
    if (row >= BSZ * TT) return;
    const float* xr = x + (size_t)row * DIN0;
    float v[DIN0];
    float mu = 0.f;
#pragma unroll
    for (int k = 0; k < DIN0; ++k) { v[k] = xr[k]; mu += v[k]; }
    mu *= (1.f / DIN0);
    float var = 0.f;
#pragma unroll
    for (int k = 0; k < DIN0; ++k) { float d = v[k] - mu; var += d * d; }
    var *= (1.f / DIN0);
    float inv = rsqrtf(var + LN_EPS);
#pragma unroll
    for (int k = 0; k < DIN0; ++k)
        d_xn[(size_t)row * DIN0 + k] = (v[k] - mu) * inv * g[k] + b[k];
}

// ---------------- tensor-core BiLSTM recurrence v4 ----------------
// v3 (shuffle-free, nb-outer) + B-fragments cached in REGISTERS across the whole
// time loop (first 8 k-chunks; L0's 9th chunk = folded x cols stays in-loop).
#define XPST 516

template <int LAYER>
__global__ __launch_bounds__(512, 1)
void lstm_tc2_kernel(const float* __restrict__ xn,     // L0 input [B][T][6]
                     const __half* __restrict__ xph,   // L1 input xp [B*T][1024]
                     const __half* __restrict__ Wmat,  // L0: [2][512][144]; L1: [2][512][128]
                     const float* __restrict__ biasp,  // [2][512] unit-major
                     __half* __restrict__ hout) {      // [B][T][256] fp16
    constexpr int KDIM = (LAYER == 0) ? 144 : 128;
    constexpr int KC   = KDIM / 16;
    constexpr int BSTX = (LAYER == 0) ? 152 : 136;

    extern __shared__ __align__(16) unsigned char smraw[];
    __half* Bs = reinterpret_cast<__half*>(smraw);     // [512][BSTX]
    __half* Hs = Bs + 512 * BSTX;                      // [2][16][BSTX]
    __half* Xp = Hs + 2 * 16 * BSTX;                   // [2][16][XPST] (L1 only)

    const int tid  = threadIdx.x;
    const int warp = tid >> 5;
    const int lane = tid & 31;
    const int dir  = blockIdx.y;
    const int bb0  = blockIdx.x * 16;
    const int j    = tid & 127;
    const int rg   = tid >> 7;
    const int nb0c = warp * 32;
    const int half = dir * 128;

    {
        const __half* src = Wmat + (size_t)dir * 512 * KDIM;
        constexpr int CH = KDIM / 8;
        for (int i = tid; i < 512 * CH; i += 512) {
            int n = i / CH, seg = i - n * CH;
            cp16(&Bs[n * BSTX + seg * 8], src + (size_t)n * KDIM + seg * 8);
        }
    }
    for (int i = tid; i < 2 * 16 * BSTX; i += 512) Hs[i] = __float2half(0.f);

    {
        const int tt0 = dir ? (TT - 1) : 0;
        if (LAYER == 0) {
            if (tid < 16 * DIN0) {
                int r = tid / DIN0, k = tid - r * DIN0;
                Hs[r * BSTX + 128 + k] =
                    __float2half(xn[((size_t)(bb0 + r) * TT + tt0) * DIN0 + k]);
            }
        } else {
#pragma unroll
            for (int rr = 0; rr < 4; ++rr) {
                int row = rg * 4 + rr;
                cp8(&Xp[row * XPST + j * 4],
                    &xph[((size_t)(bb0 + row) * TT + tt0) * 1024 + half * 4 + j * 4]);
            }
            asm volatile("cp.async.commit_group;\n");
        }
    }
    asm volatile("cp.async.wait_group 0;\n" ::: "memory");

    const int uu = lane & 3;
    const int r0 = lane >> 2;
    float4 bq[2];
#pragma unroll
    for (int nb = 0; nb < 2; ++nb)
        bq[nb] = reinterpret_cast<const float4*>(biasp + dir * 512)[warp * 8 + nb * 4 + uu];

    float c[4] = {0.f, 0.f, 0.f, 0.f};
    __syncthreads();   // Bs (weights) complete

    // ---- cache Whh B-fragments in registers for the whole time loop ----
    uint32_t rbf[8][2][4];
#pragma unroll
    for (int nb = 0; nb < 2; ++nb) {
#pragma unroll
        for (int kc = 0; kc < 8; ++kc) {
            uint32_t sb = (uint32_t)__cvta_generic_to_shared(
                &Bs[(nb0c + nb * 16 + ((lane >> 4) & 1) * 8 + (lane & 7)) * BSTX +
                    ((lane >> 3) & 1) * 8 + kc * 16]);
            asm volatile("ldmatrix.sync.aligned.m8n8.x4.shared.b16 {%0,%1,%2,%3},[%4];"
                         : "=r"(rbf[kc][nb][0]), "=r"(rbf[kc][nb][1]),
                           "=r"(rbf[kc][nb][2]), "=r"(rbf[kc][nb][3]) : "r"(sb));
        }
    }

    for (int s = 0; s < TT; ++s) {
        const int cur = s & 1, nxt = (s + 1) & 1;

        if (s + 1 < TT) {
            const int ttn = dir ? (TT - 2 - s) : (s + 1);
            if (LAYER == 0) {
                if (tid < 16 * DIN0) {
                    int r = tid / DIN0, k = tid - r * DIN0;
                    Hs[nxt * 16 * BSTX + r * BSTX + 128 + k] =
                        __float2half(xn[((size_t)(bb0 + r) * TT + ttn) * DIN0 + k]);
                }
            } else {
#pragma unroll
                for (int rr = 0; rr < 4; ++rr) {
                    int row = rg * 4 + rr;
                    cp8(&Xp[nxt * 16 * XPST + row * XPST + j * 4],
                        &xph[((size_t)(bb0 + row) * TT + ttn) * 1024 + half * 4 + j * 4]);
                }
            }
        }
        if (LAYER == 1) asm volatile("cp.async.commit_group;\n");

        if (s > 0) {
            const int tts = dir ? (TT - s) : (s - 1);
#pragma unroll
            for (int rr = 0; rr < 4; ++rr) {
                int row = rg * 4 + rr;
                hout[((size_t)(bb0 + row) * TT + tts) * 256 + half + j] =
                    Hs[cur * 16 * BSTX + row * BSTX + j];
            }
        }

        // ---- MMAs: A-fragments per kc (in-loop), B from registers ----
        const __half* hsc = Hs + cur * 16 * BSTX;
        float acc[4][4];
#pragma unroll
        for (int q = 0; q < 4; ++q) { acc[q][0] = acc[q][1] = acc[q][2] = acc[q][3] = 0.f; }

#pragma unroll
        for (int kc = 0; kc < KC; ++kc) {
            uint32_t ra0, ra1, ra2, ra3;
            uint32_t sa = (uint32_t)__cvta_generic_to_shared(
                &hsc[(lane & 15) * BSTX + (lane >> 4) * 8 + kc * 16]);
            asm volatile("ldmatrix.sync.aligned.m8n8.x4.shared.b16 {%0,%1,%2,%3},[%4];"
                         : "=r"(ra0), "=r"(ra1), "=r"(ra2), "=r"(ra3) : "r"(sa));
#pragma unroll
            for (int nb = 0; nb < 2; ++nb) {
                uint32_t rb0, rb1, rb2, rb3;
                if (kc < 8) {
                    rb0 = rbf[kc][nb][0]; rb1 = rbf[kc][nb][1];
                    rb2 = rbf[kc][nb][2]; rb3 = rbf[kc][nb][3];
                } else {   // L0 only: folded x columns
                    uint32_t sb = (uint32_t)__cvta_generic_to_shared(
                        &Bs[(nb0c + nb * 16 + ((lane >> 4) & 1) * 8 + (lane & 7)) * BSTX +
                            ((lane >> 3) & 1) * 8 + kc * 16]);
                    asm volatile("ldmatrix.sync.aligned.m8n8.x4.shared.b16 {%0,%1,%2,%3},[%4];"
                                 : "=r"(rb0), "=r"(rb1), "=r"(rb2), "=r"(rb3) : "r"(sb));
                }
                asm volatile("mma.sync.aligned.m16n8k16.row.col.f32.f16.f16.f32 "
                             "{%0,%1,%2,%3},{%4,%5,%6,%7},{%8,%9},{%0,%1,%2,%3};"
                             : "+f"(acc[nb * 2][0]), "+f"(acc[nb * 2][1]),
                               "+f"(acc[nb * 2][2]), "+f"(acc[nb * 2][3])
                             : "r"(ra0), "r"(ra1), "r"(ra2), "r"(ra3), "r"(rb0), "r"(rb1));
                asm volatile("mma.sync.aligned.m16n8k16.row.col.f32.f16.f16.f32 "
                             "{%0,%1,%2,%3},{%4,%5,%6,%7},{%8,%9},{%0,%1,%2,%3};"
                             : "+f"(acc[nb * 2 + 1][0]), "+f"(acc[nb * 2 + 1][1]),
                               "+f"(acc[nb * 2 + 1][2]), "+f"(acc[nb * 2 + 1][3])
                             : "r"(ra0), "r"(ra1), "r"(ra2), "r"(ra3), "r"(rb2), "r"(rb3));
            }
        }

        // ---- activation (shuffle-free) ----
        __half* hsn = Hs + nxt * 16 * BSTX;
#pragma unroll
        for (int nb = 0; nb < 2; ++nb) {
            const int jq = warp * 8 + nb * 4 + uu;
            const int pif = warp * 32 + nb * 16 + uu * 2;   // xp cols (i,f); (g,o) at +8
#pragma unroll
            for (int rh = 0; rh < 2; ++rh) {
                const int row = r0 + rh * 8;
                float ai = acc[nb * 2][rh * 2 + 0] + bq[nb].x;
                float af = acc[nb * 2][rh * 2 + 1] + bq[nb].y;
                float ag = acc[nb * 2 + 1][rh * 2 + 0] + bq[nb].z;
                float ao = acc[nb * 2 + 1][rh * 2 + 1] + bq[nb].w;
                if (LAYER == 1) {
                    const __half2 xif = *reinterpret_cast<const __half2*>(
                        &Xp[cur * 16 * XPST + row * XPST + pif]);
                    const __half2 xgo = *reinterpret_cast<const __half2*>(
                        &Xp[cur * 16 * XPST + row * XPST + pif + 8]);
                    ai += __low2float(xif);  af += __high2float(xif);
                    ag += __low2float(xgo);  ao += __high2float(xgo);
                }
                float ii = sig_fast(ai);
                float ff = sig_fast(af);
                float G  = tanh_fast(ag);
                float oo = sig_fast(ao);
                const int cell = nb * 2 + rh;
                c[cell] = ff * c[cell] + ii * G;
                float hv = oo * tanh_fast(c[cell]);
                hsn[row * BSTX + jq] = __float2half(hv);
            }
        }

        if (LAYER == 1) asm volatile("cp.async.wait_group 0;\n" ::: "memory");
        __syncthreads();
    }

    {
        const int tts = dir ? 0 : (TT - 1);
#pragma unroll
        for (int rr = 0; rr < 4; ++rr) {
            int row = rg * 4 + rr;
            hout[((size_t)(bb0 + row) * TT + tts) * 256 + half + j] =
                Hs[((TT) & 1) * 16 * BSTX + row * BSTX + j];
        }
    }
}

#define LSTM0_SMEM ((512 * 152 + 2 * 16 * 152) * 2)
#define LSTM1_SMEM ((512 * 136 + 2 * 16 * 136) * 2 + 2 * 16 * XPST * 2)

// ================= xp GEMM (R11 best config: 256 thr, warp tile 32M x 64N) ==========
#define G2ST 264
#define GEMM2_SMEM (3 * 128 * G2ST * 2)   // 202752 bytes

__device__ __forceinline__ void g2_stage(__half* dst, const __half* g, int tid) {
#pragma unroll
    for (int it = 0; it < 16; ++it) {
        int i = tid + it * 256;
        int row = i >> 5, seg = i & 31;
        cp16(&dst[row * G2ST + seg * 8], g + (size_t)row * 256 + seg * 8);
    }
}

__global__ __launch_bounds__(256, 1)
void xp_gemm2_kernel(const __half* __restrict__ A,   // [M][256]
                     const __half* __restrict__ Bw,  // [1024][256]
                     __half* __restrict__ C) {       // [M][1024] fp16
    extern __shared__ __align__(16) __half sm[];
    __half* Bs = sm;                   // [128][G2ST]
    __half* As = sm + 128 * G2ST;      // [2][128][G2ST]

    const int tid  = threadIdx.x;
    const int warp = tid >> 5;
    const int lane = tid & 31;
    const int warpM = warp >> 1;
    const int warpN = warp & 1;
    const int    nBase = blockIdx.x * 128;
    const size_t mGrp  = (size_t)blockIdx.y * 16;

    g2_stage(Bs, Bw + (size_t)nBase * 256, tid);
    g2_stage(As, A + mGrp * 128 * 256, tid);
    asm volatile("cp.async.commit_group;\n");
    g2_stage(As + 128 * G2ST, A + (mGrp + 1) * 128 * 256, tid);
    asm volatile("cp.async.commit_group;\n");

    for (int t = 0; t < 16; ++t) {
        if (t < 15) asm volatile("cp.async.wait_group 1;\n");
        else        asm volatile("cp.async.wait_group 0;\n");
        __syncthreads();

        const __half* as = As + (t & 1) * 128 * G2ST;
        float acc[16][4];
#pragma unroll
        for (int q = 0; q < 16; ++q) { acc[q][0] = acc[q][1] = acc[q][2] = acc[q][3] = 0.f; }

#pragma unroll
        for (int kf = 0; kf < 16; ++kf) {
            uint32_t ra[2][4];
#pragma unroll
            for (int mf = 0; mf < 2; ++mf) {
                uint32_t saddrA = (uint32_t)__cvta_generic_to_shared(
                    &as[(warpM * 32 + mf * 16 + (lane & 15)) * G2ST +
                        (lane >> 4) * 8 + kf * 16]);
                asm volatile("ldmatrix.sync.aligned.m8n8.x4.shared.b16 {%0,%1,%2,%3},[%4];"
                             : "=r"(ra[mf][0]), "=r"(ra[mf][1]),
                               "=r"(ra[mf][2]), "=r"(ra[mf][3]) : "r"(saddrA));
            }
#pragma unroll
            for (int nb = 0; nb < 4; ++nb) {
                uint32_t rb0, rb1, rb2, rb3;
                uint32_t saddrB = (uint32_t)__cvta_generic_to_shared(
                    &Bs[(warpN * 64 + nb * 16 + ((lane >> 4) & 1) * 8 + (lane & 7)) * G2ST +
                        ((lane >> 3) & 1) * 8 + kf * 16]);
                asm volatile("ldmatrix.sync.aligned.m8n8.x4.shared.b16 {%0,%1,%2,%3},[%4];"
                             : "=r"(rb0), "=r"(rb1), "=r"(rb2), "=r"(rb3) : "r"(saddrB));
#pragma unroll
                for (int mf = 0; mf < 2; ++mf) {
                    asm volatile("mma.sync.aligned.m16n8k16.row.col.f32.f16.f16.f32 "
                                 "{%0,%1,%2,%3},{%4,%5,%6,%7},{%8,%9},{%0,%1,%2,%3};"
                                 : "+f"(acc[mf * 8 + nb * 2][0]), "+f"(acc[mf * 8 + nb * 2][1]),
                                   "+f"(acc[mf * 8 + nb * 2][2]), "+f"(acc[mf * 8 + nb * 2][3])
                                 : "r"(ra[mf][0]), "r"(ra[mf][1]), "r"(ra[mf][2]), "r"(ra[mf][3]),
                                   "r"(rb0), "r"(rb1));
                    asm volatile("mma.sync.aligned.m16n8k16.row.col.f32.f16.f16.f32 "
                                 "{%0,%1,%2,%3},{%4,%5,%6,%7},{%8,%9},{%0,%1,%2,%3};"
                                 : "+f"(acc[mf * 8 + nb * 2 + 1][0]), "+f"(acc[mf * 8 + nb * 2 + 1][1]),
                                   "+f"(acc[mf * 8 + nb * 2 + 1][2]), "+f"(acc[mf * 8 + nb * 2 + 1][3])
                                 : "r"(ra[mf][0]), "r"(ra[mf][1]), "r"(ra[mf][2]), "r"(ra[mf][3]),
                                   "r"(rb2), "r"(rb3));
                }
            }
        }

        {
            const size_t rowA = (mGrp + t) * 128 + warpM * 32 + (lane >> 2);
            const int    colA = nBase + warpN * 64 + (lane & 3) * 2;
#pragma unroll
            for (int mf = 0; mf < 2; ++mf) {
#pragma unroll
                for (int nb = 0; nb < 4; ++nb) {
#pragma unroll
                    for (int h = 0; h < 2; ++h) {
                        const int q = mf * 8 + nb * 2 + h;
                        const size_t r0 = rowA + mf * 16;
                        const int    cc = colA + nb * 16 + h * 8;
                        *reinterpret_cast<__half2*>(&C[r0 * 1024 + cc]) =
                            __floats2half2_rn(acc[q][0], acc[q][1]);
                        *reinterpret_cast<__half2*>(&C[(r0 + 8) * 1024 + cc]) =
                            __floats2half2_rn(acc[q][2], acc[q][3]);
                    }
                }
            }
        }
        __syncthreads();

        if (t + 2 < 16)
            g2_stage(As + (t & 1) * 128 * G2ST, A + (mGrp + t + 2) * 128 * 256, tid);
        asm volatile("cp.async.commit_group;\n");
    }
}

// ---------------- tensor-core attention scores (unchanged) ----------------
#define BS_STRIDE 264
#define AS_STRIDE 72
#define GEMM_SMEM ((128 * BS_STRIDE + 2 * 128 * AS_STRIDE) * 2)

__global__ __launch_bounds__(256)
void scores_mma_kernel(const __half* __restrict__ A,    // d_h1h [M][256]
                       const __half* __restrict__ Bw,   // d_Wa16 [128][256]
                       const float* __restrict__ ba1,
                       const float* __restrict__ Wa2,
                       const float* __restrict__ ba2,
                       float* __restrict__ scores) {
    extern __shared__ __align__(16) __half sm[];
    __half* Bs = sm;
    __half* As = sm + 128 * BS_STRIDE;
    __shared__ float ba1s[128];
    __shared__ float wa2s[128];

    const int tid  = threadIdx.x;
    const int warp = tid >> 5;
    const int lane = tid & 31;
    const size_t mBase = (size_t)blockIdx.x * 128;

    if (tid < 128) { ba1s[tid] = ba1[tid]; wa2s[tid] = Wa2[tid]; }

    {
        for (int i = tid; i < 4096; i += 256) {
            int row = i >> 5, seg = i & 31;
            cp16(&Bs[row * BS_STRIDE + seg * 8], Bw + (size_t)row * 256 + seg * 8);
        }
        const __half* ag = A + mBase * 256;
        for (int i = tid; i < 1024; i += 256) {
            int row = i >> 3, seg = i & 7;
            cp16(&As[row * AS_STRIDE + seg * 8], ag + (size_t)row * 256 + seg * 8);
        }
        asm volatile("cp.async.commit_group;\n");
        const __half* ag1 = A + mBase * 256 + 64;
        for (int i = tid; i < 1024; i += 256) {
            int row = i >> 3, seg = i & 7;
            cp16(&As[(128 + row) * AS_STRIDE + seg * 8], ag1 + (size_t)row * 256 + seg * 8);
        }
        asm volatile("cp.async.commit_group;\n");
    }

    float acc[16][4];
#pragma unroll
    for (int q = 0; q < 16; ++q) { acc[q][0] = acc[q][1] = acc[q][2] = acc[q][3] = 0.f; }

    for (int kc = 0; kc < 4; ++kc) {
        if (kc < 3) asm volatile("cp.async.wait_group 1;\n");
        else        asm volatile("cp.async.wait_group 0;\n");
        __syncthreads();

        const __half* as = As + (kc & 1) * 128 * AS_STRIDE;
#pragma unroll
        for (int kf = 0; kf < 4; ++kf) {
            uint32_t ra0, ra1, ra2, ra3;
            uint32_t saddrA = (uint32_t)__cvta_generic_to_shared(
                &as[(warp * 16 + (lane & 15)) * AS_STRIDE + (lane >> 4) * 8 + kf * 16]);
            asm volatile("ldmatrix.sync.aligned.m8n8.x4.shared.b16 {%0,%1,%2,%3},[%4];"
                         : "=r"(ra0), "=r"(ra1), "=r"(ra2), "=r"(ra3) : "r"(saddrA));
#pragma unroll
            for (int nb = 0; nb < 8; ++nb) {
                uint32_t rb0, rb1, rb2, rb3;
                uint32_t saddrB = (uint32_t)__cvta_generic_to_shared(
                    &Bs[(nb * 16 + ((lane >> 4) & 1) * 8 + (lane & 7)) * BS_STRIDE +
                        ((lane >> 3) & 1) * 8 + kc * 64 + kf * 16]);
                asm volatile("ldmatrix.sync.aligned.m8n8.x4.shared.b16 {%0,%1,%2,%3},[%4];"
                             : "=r"(rb0), "=r"(rb1), "=r"(rb2), "=r"(rb3) : "r"(saddrB));
                asm volatile("mma.sync.aligned.m16n8k16.row.col.f32.f16.f16.f32 "
                             "{%0,%1,%2,%3},{%4,%5,%6,%7},{%8,%9},{%0,%1,%2,%3};"
                             : "+f"(acc[nb * 2][0]), "+f"(acc[nb * 2][1]),
                               "+f"(acc[nb * 2][2]), "+f"(acc[nb * 2][3])
                             : "r"(ra0), "r"(ra1), "r"(ra2), "r"(ra3), "r"(rb0), "r"(rb1));
                asm volatile("mma.sync.aligned.m16n8k16.row.col.f32.f16.f16.f32 "
                             "{%0,%1,%2,%3},{%4,%5,%6,%7},{%8,%9},{%0,%1,%2,%3};"
                             : "+f"(acc[nb * 2 + 1][0]), "+f"(acc[nb * 2 + 1][1]),
                               "+f"(acc[nb * 2 + 1][2]), "+f"(acc[nb * 2 + 1][3])
                             : "r"(ra0), "r"(ra1), "r"(ra2), "r"(ra3), "r"(rb2), "r"(rb3));
            }
        }
        __syncthreads();

        if (kc < 2) {
            const __half* ag = A + mBase * 256 + (kc + 2) * 64;
            for (int i = tid; i < 1024; i += 256) {
                int row = i >> 3, seg = i & 7;
                cp16(&As[((kc & 1) * 128 + row) * AS_STRIDE + seg * 8],
                     ag + (size_t)row * 256 + seg * 8);
            }
            asm volatile("cp.async.commit_group;\n");
        }
    }

    const float b2 = ba2[0];
    float p0 = 0.f, p1 = 0.f;
#pragma unroll
    for (int nb = 0; nb < 8; ++nb) {
#pragma unroll
        for (int h = 0; h < 2; ++h) {
            const int q = nb * 2 + h;
            const int c0 = nb * 16 + h * 8 + (lane & 3) * 2;
            const int c1 = c0 + 1;
            p0 += tanh_fast(acc[q][0] + ba1s[c0]) * wa2s[c0]
                + tanh_fast(acc[q][1] + ba1s[c1]) * wa2s[c1];
            p1 += tanh_fast(acc[q][2] + ba1s[c0]) * wa2s[c0]
                + tanh_fast(acc[q][3] + ba1s[c1]) * wa2s[c1];
        }
    }
    p0 += __shfl_xor_sync(0xffffffffu, p0, 1);
    p0 += __shfl_xor_sync(0xffffffffu, p0, 2);
    p1 += __shfl_xor_sync(0xffffffffu, p1, 1);
    p1 += __shfl_xor_sync(0xffffffffu, p1, 2);
    if ((lane & 3) == 0) {
        const size_t row = mBase + warp * 16 + (lane >> 2);
        scores[row]     = p0 + b2;
        scores[row + 8] = p1 + b2;
    }
}

// ---------------- softmax over T + context + LN head + output (unchanged) ----------
__global__ __launch_bounds__(256) void finish_kernel(const float* __restrict__ Wf1,
                                                     const float* __restrict__ bf1,
                                                     const float* __restrict__ g2,
                                                     const float* __restrict__ b2v,
                                                     const float* __restrict__ Wf2,
                                                     const float* __restrict__ bf2,
                                                     float* __restrict__ out) {
    const int b = blockIdx.x;
    const int tid = threadIdx.x;
    __shared__ float attn[256];
    __shared__ __align__(16) float ctx[256];
    __shared__ float zs[128];
    __shared__ float red[8];

    float s = d_scores[b * TT + tid];

    float v = s;
#pragma unroll
    for (int o = 16; o; o >>= 1) v = fmaxf(v, __shfl_xor_sync(0xffffffffu, v, o));
    if ((tid & 31) == 0) red[tid >> 5] = v;
    __syncthreads();
    float mx = fmaxf(fmaxf(fmaxf(red[0], red[1]), fmaxf(red[2], red[3])),
                     fmaxf(fmaxf(red[4], red[5]), fmaxf(red[6], red[7])));
    float e = __expf(s - mx);
    float v2 = e;
#pragma unroll
    for (int o = 16; o; o >>= 1) v2 += __shfl_xor_sync(0xffffffffu, v2, o);
    __syncthreads();
    if ((tid & 31) == 0) red[tid >> 5] = v2;
    __syncthreads();
    float sum = red[0] + red[1] + red[2] + red[3] + red[4] + red[5] + red[6] + red[7];
    attn[tid] = e / sum;
    __syncthreads();

    float acc = 0.f;
    const __half* hb = d_h1h + (size_t)b * TT * 256;
    for (int t = 0; t < TT; ++t) acc += __half2float(hb[t * 256 + tid]) * attn[t];
    ctx[tid] = acc;
    __syncthreads();

    float z = 0.f;
    if (tid < 128) {
        z = bf1[tid];
        const float4* wf = reinterpret_cast<const float4*>(Wf1 + (size_t)tid * 256);
        const float4* cx = reinterpret_cast<const float4*>(ctx);
#pragma unroll 8
        for (int k4 = 0; k4 < 64; ++k4) {
            float4 w = wf[k4];
            float4 c4 = cx[k4];
            z += w.x * c4.x + w.y * c4.y + w.z * c4.z + w.w * c4.w;
        }
        float s1 = z, s2 = z * z;
#pragma unroll
        for (int o = 16; o; o >>= 1) {
            s1 += __shfl_xor_sync(0xffffffffu, s1, o);
            s2 += __shfl_xor_sync(0xffffffffu, s2, o);
        }
        if ((tid & 31) == 0) { red[tid >> 5] = s1; red[4 + (tid >> 5)] = s2; }
    }
    __syncthreads();
    if (tid < 128) {
        float mu = (red[0] + red[1] + red[2] + red[3]) * (1.f / 128.f);
        float ms = (red[4] + red[5] + red[6] + red[7]) * (1.f / 128.f);
        float var = ms - mu * mu;
        float zn = (z - mu) * rsqrtf(var + LN_EPS) * g2[tid] + b2v[tid];
        zs[tid] = fmaxf(zn, 0.f);
    }
    __syncthreads();
    if (tid < 5) {
        float y = bf2[tid];
        const float* w = Wf2 + tid * 128;
#pragma unroll 8
        for (int k = 0; k < 128; ++k) y += w[k] * zs[k];
        out[b * 5 + tid] = y;
    }
}

// ---------------- launch ----------------
extern "C" void kernel_launch(void* const* d_in, const int* in_sizes, int n_in,
                              void* d_out, int out_size) {
    const float* x     = (const float*)d_in[0];
    const float* ln_g  = (const float*)d_in[1];
    const float* ln_b  = (const float*)d_in[2];
    const float* Wih0  = (const float*)d_in[3];
    const float* Whh0  = (const float*)d_in[4];
    const float* bih0  = (const float*)d_in[5];
    const float* bhh0  = (const float*)d_in[6];
    const float* Wih1  = (const float*)d_in[7];
    const float* Whh1  = (const float*)d_in[8];
    const float* bih1  = (const float*)d_in[9];
    const float* bhh1  = (const float*)d_in[10];
    const float* Wa1   = (const float*)d_in[11];
    const float* ba1   = (const float*)d_in[12];
    const float* Wa2   = (const float*)d_in[13];
    const float* ba2   = (const float*)d_in[14];
    const float* Wf1   = (const float*)d_in[15];
    const float* bf1   = (const float*)d_in[16];
    const float* ln2_g = (const float*)d_in[17];
    const float* ln2_b = (const float*)d_in[18];
    const float* Wf2   = (const float*)d_in[19];
    const float* bf2   = (const float*)d_in[20];
    float* out = (float*)d_out;

    float  *p_xn, *p_b0, *p_b1, *p_sc;
    __half *p_h0h, *p_h1h, *p_xph, *p_W16, *p_W0cat, *p_Whh1h, *p_Wa16;
    cudaGetSymbolAddress((void**)&p_xn,    d_xn);
    cudaGetSymbolAddress((void**)&p_h0h,   d_h0h);
    cudaGetSymbolAddress((void**)&p_h1h,   d_h1h);
    cudaGetSymbolAddress((void**)&p_xph,   d_xph);
    cudaGetSymbolAddress((void**)&p_b0,    d_b0);
    cudaGetSymbolAddress((void**)&p_b1,    d_b1);
    cudaGetSymbolAddress((void**)&p_W16,   d_W16);
    cudaGetSymbolAddress((void**)&p_W0cat, d_W0cat);
    cudaGetSymbolAddress((void**)&p_Whh1h, d_Whh1h);
    cudaGetSymbolAddress((void**)&p_Wa16,  d_Wa16);
    cudaGetSymbolAddress((void**)&p_sc,    d_scores);

    cudaFuncSetAttribute(xp_gemm2_kernel,
                         cudaFuncAttributeMaxDynamicSharedMemorySize, GEMM2_SMEM);
    cudaFuncSetAttribute(scores_mma_kernel,
                         cudaFuncAttributeMaxDynamicSharedMemorySize, GEMM_SMEM);
    cudaFuncSetAttribute(lstm_tc2_kernel<0>,
                         cudaFuncAttributeMaxDynamicSharedMemorySize, LSTM0_SMEM);
    cudaFuncSetAttribute(lstm_tc2_kernel<1>,
                         cudaFuncAttributeMaxDynamicSharedMemorySize, LSTM1_SMEM);

    pack_kernel<<<512, 512>>>(Wih0, Whh0, bih0, bhh0, Wih1, Whh1, bih1, bhh1, Wa1);
    ln_kernel<<<(BSZ * TT + 255) / 256, 256>>>(x, ln_g, ln_b);

    dim3 gl(BSZ / 16, 2);
    lstm_tc2_kernel<0><<<gl, 512, LSTM0_SMEM>>>(p_xn, nullptr, p_W0cat, p_b0, p_h0h);

    dim3 gg(8, (BSZ * TT) / (128 * 16));    // 8 n-tiles x 128 m-groups
    xp_gemm2_kernel<<<gg, 256, GEMM2_SMEM>>>(p_h0h, p_W16, p_xph);

    lstm_tc2_kernel<1><<<gl, 512, LSTM1_SMEM>>>(nullptr, p_xph, p_Whh1h, p_b1, p_h1h);

    scores_mma_kernel<<<(BSZ * TT) / 128, 256, GEMM_SMEM>>>(p_h1h, p_Wa16, ba1, Wa2, ba2, p_sc);
    finish_kernel<<<BSZ, 256>>>(Wf1, bf1, ln2_g, ln2_b, Wf2, bf2, out);
}